// round 11
// baseline (speedup 1.0000x reference)
#include <cuda_runtime.h>
#include <cuda_bf16.h>
#include <cuda_fp16.h>
#include <cstdint>

#define NN 50000
#define EE 800000
#define LRELU 0.2f
#define LN_EPS 1e-5f
#define NBLK 148

// ------------------------- scratch (device globals) ----------------------
__device__ __align__(16) __half g_x_h[(size_t)NN * 128];    // fp16 input x
__device__ __align__(16) __half g_h_h[(size_t)NN * 128];    // fp16 layer1 out
__device__ float g_xs_f[(size_t)NN * 128];                  // fp32 xs
__device__ float g_h[(size_t)NN * 128];
__device__ float g_acc1[(size_t)NN * 128];
__device__ float g_as[NN * 4];
__device__ float g_ad[NN * 4];
__device__ __align__(16) __half2 g_Wp[2 * 384 * 64];   // [layer][col 384][k2 64] n-major
__device__ float g_biasA[2 * 128];
// CSR
__device__ int g_cnt[NN];
__device__ int g_rowptr[NN + 1];
__device__ int g_woff[NN];
__device__ int g_csrc[EE];
__device__ int g_bsum[NBLK];
// software grid barrier state
__device__ int g_barc[4];
__device__ int g_barf[4];

// ------------------------- helpers ---------------------------------------
__device__ __forceinline__ uint32_t smem_u32(const void* p)
{
    return (uint32_t)__cvta_generic_to_shared(p);
}

#define LDSM_X4(d0, d1, d2, d3, addr)                                            \
    asm volatile("ldmatrix.sync.aligned.m8n8.x4.shared.b16 {%0,%1,%2,%3}, [%4];" \
                 : "=r"(d0), "=r"(d1), "=r"(d2), "=r"(d3) : "r"(addr))

#define MMA16816(C, A0, A1, A2, A3, B0, B1)                                  \
    asm volatile("mma.sync.aligned.m16n8k16.row.col.f32.f16.f16.f32 "        \
                 "{%0,%1,%2,%3}, {%4,%5,%6,%7}, {%8,%9}, {%0,%1,%2,%3};"     \
                 : "+f"((C)[0]), "+f"((C)[1]), "+f"((C)[2]), "+f"((C)[3])    \
                 : "r"(A0), "r"(A1), "r"(A2), "r"(A3), "r"(B0), "r"(B1))

#define CP_ASYNC16(dst, src, sz)                                             \
    asm volatile("cp.async.cg.shared.global [%0], [%1], 16, %2;"             \
                 :: "r"(dst), "l"(src), "r"(sz))

// ------------------------- merged prep: x->fp16 + weight pack ------------
__global__ void prep_all(const float* __restrict__ X,
                         const float* __restrict__ W1s, const float* __restrict__ W1d,
                         const float* __restrict__ Wl1, const float* __restrict__ bl1,
                         const float* __restrict__ b1,
                         const float* __restrict__ W2s, const float* __restrict__ W2d,
                         const float* __restrict__ Wl2, const float* __restrict__ bl2,
                         const float* __restrict__ b2)
{
    if (blockIdx.x < 3125) {
        int i = blockIdx.x * 256 + threadIdx.x;           // < 800000 = NN*16
        const float4* p = (const float4*)X + (size_t)i * 2;
        float4 a = p[0], b = p[1];
        __half2 h[4];
        h[0] = __floats2half2_rn(a.x, a.y); h[1] = __floats2half2_rn(a.z, a.w);
        h[2] = __floats2half2_rn(b.x, b.y); h[3] = __floats2half2_rn(b.z, b.w);
        *(uint4*)(g_x_h + (size_t)i * 8) = *(uint4*)h;
    } else {
        int i = (blockIdx.x - 3125) * 256 + threadIdx.x;  // < 49152
        int layer = i >= 24576;
        int j = i - layer * 24576;
        int col = j >> 6, k2 = j & 63;
        int cc = col & 127;
        const float* W;
        if (col < 128)      W = layer ? W2s : W1s;
        else if (col < 256) W = layer ? Wl2 : Wl1;
        else                W = layer ? W2d : W1d;
        g_Wp[i] = __floats2half2_rn(W[(2 * k2) * 128 + cc], W[(2 * k2 + 1) * 128 + cc]);
        if (i < 128) {
            g_biasA[i]       = bl1[i] + b1[i];
            g_biasA[128 + i] = bl2[i] + b2[i];
        }
    }
}

// ------------------------- software grid barrier -------------------------
__device__ __forceinline__ void gbar(int k)
{
    __syncthreads();
    if (threadIdx.x == 0) {
        __threadfence();
        int t = atomicAdd(&g_barc[k], 1);
        if (t == NBLK - 1) {
            g_barc[k] = 0;
            __threadfence();
            atomicExch(&g_barf[k], 1);
        } else {
            while (atomicAdd(&g_barf[k], 0) == 0) __nanosleep(64);
        }
        __threadfence();
    }
    __syncthreads();
}

// ------------------------- single-kernel CSR build -----------------------
__global__ __launch_bounds__(1024) void csr_all(const int* __restrict__ src,
                                                const int* __restrict__ dst,
                                                int E, int n)
{
    __shared__ int s[1024];
    __shared__ int sb[256];
    const int tid = threadIdx.x;
    const int gid = blockIdx.x * 1024 + tid;
    const int GT = NBLK * 1024;

    for (int i = gid; i < n; i += GT) g_cnt[i] = 0;
    gbar(0);
    for (int e = gid; e < E; e += GT) atomicAdd(&g_cnt[dst[e]], 1);
    gbar(1);
    const int CH = (n + NBLK - 1) / NBLK;
    const int base = blockIdx.x * CH;
    int myc = 0;
    if (tid < CH && base + tid < n) myc = g_cnt[base + tid];
    s[tid] = myc;
    __syncthreads();
    for (int off = 1; off < 1024; off <<= 1) {
        int v = (tid >= off) ? s[tid - off] : 0;
        __syncthreads();
        s[tid] += v;
        __syncthreads();
    }
    int myincl = s[tid];
    if (tid == 1023) g_bsum[blockIdx.x] = s[1023];
    gbar(2);
    if (tid < 256) sb[tid] = (tid < NBLK) ? g_bsum[tid] : 0;
    __syncthreads();
    for (int off = 1; off < 256; off <<= 1) {
        int v = 0;
        if (tid < 256 && tid >= off) v = sb[tid - off];
        __syncthreads();
        if (tid < 256) sb[tid] += v;
        __syncthreads();
    }
    int off0 = (blockIdx.x == 0) ? 0 : sb[blockIdx.x - 1];
    if (tid < CH && base + tid < n) {
        int v = off0 + myincl - myc;
        g_rowptr[base + tid] = v;
        g_woff[base + tid] = v;
    }
    if (blockIdx.x == 0 && tid == 0) g_rowptr[n] = E;
    gbar(3);
    for (int e = gid; e < E; e += GT) {
        int d = dst[e];
        int pz = atomicAdd(&g_woff[d], 1);
        g_csrc[pz] = src[e];
    }
}

// ------------------------- fp16 GEMM: K-resident, cp.async ---------------
#define SSTR 68   // half2 stride per row (64 + 4 pad)

__global__ __launch_bounds__(256) void gemm_h(const __half* __restrict__ Ah,
                                              float* __restrict__ acc,
                                              const __half2* __restrict__ Wp,
                                              const float* __restrict__ biasv,
                                              const float* __restrict__ att_s,
                                              const float* __restrict__ att_d,
                                              int M)
{
    extern __shared__ __half2 smp[];
    __half2* As = smp;                 // [128][SSTR]
    __half2* Bs = smp + 128 * SSTR;    // [128][SSTR]

    const int tid = threadIdx.x;
    const int lane = tid & 31;
    const int warp = tid >> 5;
    const int wm = warp >> 2;
    const int wn = warp & 3;
    const int row0 = blockIdx.x * 128;
    const int y = blockIdx.y;
    const int col0 = y * 128;
    const int g = lane >> 2;
    const int t4 = lane & 3;

    #pragma unroll
    for (int j = 0; j < 8; j++) {
        int idx = tid + j * 256;
        int row = idx >> 4, part = idx & 15;
        int grow = row0 + row;
        const __half* srcp = Ah + (size_t)(grow < M ? grow : 0) * 128 + part * 8;
        uint32_t dstu = smem_u32(&As[row * SSTR + part * 4]);
        CP_ASYNC16(dstu, srcp, (grow < M) ? 16 : 0);
    }
    #pragma unroll
    for (int j = 0; j < 8; j++) {
        int idx = tid + j * 256;
        int col = idx >> 4, part = idx & 15;
        const __half2* srcp = Wp + (size_t)(col0 + col) * 64 + part * 4;
        uint32_t dstu = smem_u32(&Bs[col * SSTR + part * 4]);
        CP_ASYNC16(dstu, srcp, 16);
    }
    asm volatile("cp.async.commit_group;");

    float c[4][4][4];
    #pragma unroll
    for (int i = 0; i < 4; i++)
        #pragma unroll
        for (int j = 0; j < 4; j++)
            #pragma unroll
            for (int q = 0; q < 4; q++) c[i][j][q] = 0.f;

    uint32_t a_base[4], b_base[2];
    {
        int ar = lane & 15;
        int kq = (lane >> 4) * 4;
        #pragma unroll
        for (int mt = 0; mt < 4; mt++)
            a_base[mt] = smem_u32(&As[(wm * 64 + mt * 16 + ar) * SSTR + kq]);
        int nr = (lane & 7) + ((lane >> 4) & 1) * 8;
        int kh = ((lane >> 3) & 1) * 4;
        b_base[0] = smem_u32(&Bs[(wn * 32 + nr) * SSTR + kh]);
        b_base[1] = smem_u32(&Bs[(wn * 32 + 16 + nr) * SSTR + kh]);
    }

    asm volatile("cp.async.wait_group 0;");
    __syncthreads();

    #pragma unroll
    for (int kk = 0; kk < 8; kk++) {
        uint32_t af[4][4], b0[4], b1[4];
        #pragma unroll
        for (int mt = 0; mt < 4; mt++)
            LDSM_X4(af[mt][0], af[mt][1], af[mt][2], af[mt][3], a_base[mt] + kk * 32);
        LDSM_X4(b0[0], b0[1], b0[2], b0[3], b_base[0] + kk * 32);
        LDSM_X4(b1[0], b1[1], b1[2], b1[3], b_base[1] + kk * 32);
        #pragma unroll
        for (int mt = 0; mt < 4; mt++) {
            MMA16816(c[mt][0], af[mt][0], af[mt][1], af[mt][2], af[mt][3], b0[0], b0[1]);
            MMA16816(c[mt][1], af[mt][0], af[mt][1], af[mt][2], af[mt][3], b0[2], b0[3]);
            MMA16816(c[mt][2], af[mt][0], af[mt][1], af[mt][2], af[mt][3], b1[0], b1[1]);
            MMA16816(c[mt][3], af[mt][0], af[mt][1], af[mt][2], af[mt][3], b1[2], b1[3]);
        }
    }

    const int l2 = t4 * 2;
    if (y == 1) {
        #pragma unroll
        for (int mt = 0; mt < 4; mt++) {
            #pragma unroll
            for (int nt = 0; nt < 4; nt++) {
                int r = row0 + wm * 64 + mt * 16 + g;
                int cc = wn * 32 + nt * 8 + l2;
                float2 b2 = *(const float2*)(biasv + cc);
                if (r < M)
                    *(float2*)(acc + (size_t)r * 128 + cc) =
                        make_float2(c[mt][nt][0] + b2.x, c[mt][nt][1] + b2.y);
                if (r + 8 < M)
                    *(float2*)(acc + (size_t)(r + 8) * 128 + cc) =
                        make_float2(c[mt][nt][2] + b2.x, c[mt][nt][3] + b2.y);
            }
        }
    } else {
        const float* att = (y == 0) ? att_s : att_d;
        float* adst = (y == 0) ? g_as : g_ad;
        float2 attv[4];
        #pragma unroll
        for (int nt = 0; nt < 4; nt++)
            attv[nt] = *(const float2*)(att + wn * 32 + nt * 8 + l2);

        #pragma unroll
        for (int mt = 0; mt < 4; mt++) {
            int r = row0 + wm * 64 + mt * 16 + g;
            float p0 = 0.f, p1 = 0.f;
            #pragma unroll
            for (int nt = 0; nt < 4; nt++) {
                p0 = fmaf(c[mt][nt][0], attv[nt].x, fmaf(c[mt][nt][1], attv[nt].y, p0));
                p1 = fmaf(c[mt][nt][2], attv[nt].x, fmaf(c[mt][nt][3], attv[nt].y, p1));
                if (y == 0) {
                    int cc = wn * 32 + nt * 8 + l2;
                    if (r < M)
                        *(float2*)(g_xs_f + (size_t)r * 128 + cc) =
                            make_float2(c[mt][nt][0], c[mt][nt][1]);
                    if (r + 8 < M)
                        *(float2*)(g_xs_f + (size_t)(r + 8) * 128 + cc) =
                            make_float2(c[mt][nt][2], c[mt][nt][3]);
                }
            }
            p0 += __shfl_xor_sync(0xFFFFFFFFu, p0, 1);
            p0 += __shfl_xor_sync(0xFFFFFFFFu, p0, 2);
            p1 += __shfl_xor_sync(0xFFFFFFFFu, p1, 1);
            p1 += __shfl_xor_sync(0xFFFFFFFFu, p1, 2);
            if ((lane & 3) == 0) {
                if (r < M)     adst[r * 4 + wn] = p0;
                if (r + 8 < M) adst[(r + 8) * 4 + wn] = p1;
            }
        }
    }
}

// ------------------------- fast exp (FMA pipe) ---------------------------
__device__ __forceinline__ float fast_exp(float x)
{
    float t  = fmaf(x, 1.4426950408889634f, 12582912.0f);
    int   i  = __float_as_int(t);
    float fi = t - 12582912.0f;
    float f  = fmaf(x, 1.4426950408889634f, -fi);
    float p  = 0.0013333558f;
    p = fmaf(p, f, 0.0096181291f);
    p = fmaf(p, f, 0.0555041087f);
    p = fmaf(p, f, 0.2402265070f);
    p = fmaf(p, f, 0.6931471806f);
    p = fmaf(p, f, 1.0f);
    return __int_as_float(__float_as_int(p) + (i << 23));
}

// ------------------------- fused edge softmax-SpMM (+LN) -----------------
// warp per node; phase1: lane-parallel weights; phase2: warp-per-edge fp32
// gather (lane owns 4 features, 1 LDG.128 + 4 FMA per edge).
template <bool DO_LN>
__global__ __launch_bounds__(256) void edge_fused(float* __restrict__ io,
                                                  const float* __restrict__ gamma,
                                                  const float* __restrict__ beta,
                                                  int n)
{
    __shared__ float4 s_w4[8][32];
    __shared__ int    s_src[8][32];
    const int wid = threadIdx.x >> 5;
    const int lane = threadIdx.x & 31;
    if (DO_LN && blockIdx.x == 0 && threadIdx.x < 4)
        g_barf[threadIdx.x] = 0;                       // reset csr grid-barrier flags
    int node = (blockIdx.x * blockDim.x + threadIdx.x) >> 5;
    if (node >= n) return;

    const int rs = g_rowptr[node], re = g_rowptr[node + 1];
    const float4 ad4 = *(const float4*)(g_ad + (size_t)node * 4);
    const int h = lane >> 3;                           // head of my 4 features

    float acc[4] = {0.f, 0.f, 0.f, 0.f};
    float4 den = make_float4(0.f, 0.f, 0.f, 0.f);

    for (int base = rs; base < re; base += 32) {
        // phase 1: lane-parallel edge weights
        int e = base + lane;
        int sreg = 0;
        float4 w4 = make_float4(0.f, 0.f, 0.f, 0.f);
        if (e < re) {
            sreg = g_csrc[e];
            float4 a = *(const float4*)(g_as + (size_t)sreg * 4);
            float vx = a.x + ad4.x, vy = a.y + ad4.y;
            float vz = a.z + ad4.z, vw = a.w + ad4.w;
            vx = vx > 0.f ? vx : LRELU * vx;
            vy = vy > 0.f ? vy : LRELU * vy;
            vz = vz > 0.f ? vz : LRELU * vz;
            vw = vw > 0.f ? vw : LRELU * vw;
            w4.x = fast_exp(vx); w4.y = fast_exp(vy);
            w4.z = fast_exp(vz); w4.w = fast_exp(vw);
        }
        float4 t = w4;
        #pragma unroll
        for (int m = 16; m >= 1; m >>= 1) {
            t.x += __shfl_xor_sync(0xFFFFFFFFu, t.x, m);
            t.y += __shfl_xor_sync(0xFFFFFFFFu, t.y, m);
            t.z += __shfl_xor_sync(0xFFFFFFFFu, t.z, m);
            t.w += __shfl_xor_sync(0xFFFFFFFFu, t.w, m);
        }
        den.x += t.x; den.y += t.y; den.z += t.z; den.w += t.w;
        s_w4[wid][lane] = w4;
        s_src[wid][lane] = sreg;
        __syncwarp();

        // phase 2: warp-per-edge fp32 gather
        int cnt = min(32, re - base);
        #pragma unroll 4
        for (int it = 0; it < cnt; it++) {
            int sj = s_src[wid][it];
            float wv = ((const float*)&s_w4[wid][it])[h];
            float4 v = *((const float4*)(g_xs_f + (size_t)sj * 128) + lane);
            acc[0] = fmaf(wv, v.x, acc[0]);
            acc[1] = fmaf(wv, v.y, acc[1]);
            acc[2] = fmaf(wv, v.z, acc[2]);
            acc[3] = fmaf(wv, v.w, acc[3]);
        }
        __syncwarp();
    }

    float dh = (h < 2) ? (h == 0 ? den.x : den.y) : (h == 2 ? den.z : den.w);
    float inv = __fdividef(1.f, dh + 1e-16f);

    float4 i0 = *((const float4*)(io + (size_t)node * 128) + lane);
    float o[4];
    o[0] = fmaf(acc[0], inv, i0.x);
    o[1] = fmaf(acc[1], inv, i0.y);
    o[2] = fmaf(acc[2], inv, i0.z);
    o[3] = fmaf(acc[3], inv, i0.w);

    if (DO_LN) {
        float sum = o[0] + o[1] + o[2] + o[3];
        float sq  = fmaf(o[0], o[0], fmaf(o[1], o[1], fmaf(o[2], o[2], o[3] * o[3])));
        #pragma unroll
        for (int m = 1; m <= 16; m <<= 1) {
            sum += __shfl_xor_sync(0xFFFFFFFFu, sum, m);
            sq  += __shfl_xor_sync(0xFFFFFFFFu, sq, m);
        }
        float mean = sum * (1.f / 128.f);
        float var  = sq * (1.f / 128.f) - mean * mean;
        float rstd = rsqrtf(var + LN_EPS);
        float4 ga = *((const float4*)gamma + lane);
        float4 ba = *((const float4*)beta + lane);
        float r0 = fmaxf(0.f, (o[0] - mean) * rstd * ga.x + ba.x);
        float r1 = fmaxf(0.f, (o[1] - mean) * rstd * ga.y + ba.y);
        float r2 = fmaxf(0.f, (o[2] - mean) * rstd * ga.z + ba.z);
        float r3 = fmaxf(0.f, (o[3] - mean) * rstd * ga.w + ba.w);
        *((float4*)(g_h + (size_t)node * 128) + lane) = make_float4(r0, r1, r2, r3);
        __half2 p0 = __floats2half2_rn(r0, r1);
        __half2 p1 = __floats2half2_rn(r2, r3);
        uint2 u;
        u.x = *(uint32_t*)&p0;
        u.y = *(uint32_t*)&p1;
        *(uint2*)(g_h_h + (size_t)node * 128 + lane * 4) = u;
    } else {
        *((float4*)(io + (size_t)node * 128) + lane) = make_float4(o[0], o[1], o[2], o[3]);
    }
}

// ------------------------- driver ----------------------------------------
extern "C" void kernel_launch(void* const* d_in, const int* in_sizes, int n_in,
                              void* d_out, int out_size)
{
    const float* x        = (const float*)d_in[0];
    const int*   ei       = (const int*)  d_in[1];
    const float* W1_src   = (const float*)d_in[2];
    const float* W1_dst   = (const float*)d_in[3];
    const float* att1_src = (const float*)d_in[4];
    const float* att1_dst = (const float*)d_in[5];
    const float* b1       = (const float*)d_in[6];
    const float* Wl1      = (const float*)d_in[7];
    const float* bl1      = (const float*)d_in[8];
    const float* gamma    = (const float*)d_in[9];
    const float* beta     = (const float*)d_in[10];
    const float* W2_src   = (const float*)d_in[11];
    const float* W2_dst   = (const float*)d_in[12];
    const float* att2_src = (const float*)d_in[13];
    const float* att2_dst = (const float*)d_in[14];
    const float* b2       = (const float*)d_in[15];
    const float* Wl2      = (const float*)d_in[16];
    const float* bl2      = (const float*)d_in[17];
    float* out = (float*)d_out;

    const int n = NN;
    const int E = EE;
    const int* src = ei;
    const int* dst = ei + E;

    void* p;
    cudaGetSymbolAddress(&p, g_acc1);  float* acc1 = (float*)p;
    cudaGetSymbolAddress(&p, g_Wp);    __half2* wp = (__half2*)p;
    cudaGetSymbolAddress(&p, g_biasA); float* bias = (float*)p;
    cudaGetSymbolAddress(&p, g_x_h);   __half* xh = (__half*)p;
    cudaGetSymbolAddress(&p, g_h_h);   __half* hh = (__half*)p;

    const int SMEM = 2 * 128 * SSTR * 4;   // 69632 B
    cudaFuncSetAttribute(gemm_h, cudaFuncAttributeMaxDynamicSharedMemorySize, SMEM);

    dim3 gemm_grid((n + 127) / 128, 3);
    int node_blocks = (n * 32 + 255) / 256;

    prep_all<<<3317, 256>>>(x, W1_src, W1_dst, Wl1, bl1, b1,
                            W2_src, W2_dst, Wl2, bl2, b2);                    // 1
    csr_all<<<NBLK, 1024>>>(src, dst, E, n);                                  // 2
    gemm_h<<<gemm_grid, 256, SMEM>>>(xh, acc1, wp, bias,
                                     att1_src, att1_dst, n);                  // 3
    edge_fused<true><<<node_blocks, 256>>>(acc1, gamma, beta, n);             // 4 (ncu)
    gemm_h<<<gemm_grid, 256, SMEM>>>(hh, out, wp + 384 * 64, bias + 128,
                                     att2_src, att2_dst, n);                  // 5
    edge_fused<false><<<node_blocks, 256>>>(out, nullptr, nullptr, n);        // 6
}

// round 12
// speedup vs baseline: 1.0909x; 1.0909x over previous
#include <cuda_runtime.h>
#include <cuda_bf16.h>
#include <cuda_fp16.h>
#include <cstdint>

#define NN 50000
#define EE 800000
#define LRELU 0.2f
#define LN_EPS 1e-5f
#define NBLK 148

// ------------------------- scratch (device globals) ----------------------
__device__ __align__(16) __half g_x_h[(size_t)NN * 128];    // fp16 input x
__device__ __align__(16) __half g_h_h[(size_t)NN * 128];    // fp16 layer1 out
__device__ __align__(16) __half g_xs_h[(size_t)NN * 128];   // fp16 xs
__device__ float g_acc1[(size_t)NN * 128];
__device__ float g_as[NN * 4];
__device__ float g_ad[NN * 4];
__device__ __align__(16) __half2 g_Wp[2 * 384 * 64];   // [layer][col 384][k2 64] n-major
__device__ float g_biasA[2 * 128];
// CSR
__device__ int g_cnt[NN];
__device__ int g_rowptr[NN + 1];
__device__ int g_woff[NN];
__device__ int g_csrc[EE];
__device__ int g_bsum[NBLK];
// software grid barrier state
__device__ int g_barc[4];
__device__ int g_barf[4];

// ------------------------- helpers ---------------------------------------
__device__ __forceinline__ uint32_t smem_u32(const void* p)
{
    return (uint32_t)__cvta_generic_to_shared(p);
}

#define LDSM_X4(d0, d1, d2, d3, addr)                                            \
    asm volatile("ldmatrix.sync.aligned.m8n8.x4.shared.b16 {%0,%1,%2,%3}, [%4];" \
                 : "=r"(d0), "=r"(d1), "=r"(d2), "=r"(d3) : "r"(addr))

#define MMA16816(C, A0, A1, A2, A3, B0, B1)                                  \
    asm volatile("mma.sync.aligned.m16n8k16.row.col.f32.f16.f16.f32 "        \
                 "{%0,%1,%2,%3}, {%4,%5,%6,%7}, {%8,%9}, {%0,%1,%2,%3};"     \
                 : "+f"((C)[0]), "+f"((C)[1]), "+f"((C)[2]), "+f"((C)[3])    \
                 : "r"(A0), "r"(A1), "r"(A2), "r"(A3), "r"(B0), "r"(B1))

#define CP_ASYNC16(dst, src, sz)                                             \
    asm volatile("cp.async.cg.shared.global [%0], [%1], 16, %2;"             \
                 :: "r"(dst), "l"(src), "r"(sz))

// ------------------------- merged prep: x->fp16 + weight pack ------------
__global__ void prep_all(const float* __restrict__ X,
                         const float* __restrict__ W1s, const float* __restrict__ W1d,
                         const float* __restrict__ Wl1, const float* __restrict__ bl1,
                         const float* __restrict__ b1,
                         const float* __restrict__ W2s, const float* __restrict__ W2d,
                         const float* __restrict__ Wl2, const float* __restrict__ bl2,
                         const float* __restrict__ b2)
{
    if (blockIdx.x < 3125) {
        int i = blockIdx.x * 256 + threadIdx.x;           // < 800000 = NN*16
        const float4* p = (const float4*)X + (size_t)i * 2;
        float4 a = p[0], b = p[1];
        __half2 h[4];
        h[0] = __floats2half2_rn(a.x, a.y); h[1] = __floats2half2_rn(a.z, a.w);
        h[2] = __floats2half2_rn(b.x, b.y); h[3] = __floats2half2_rn(b.z, b.w);
        *(uint4*)(g_x_h + (size_t)i * 8) = *(uint4*)h;
    } else {
        int i = (blockIdx.x - 3125) * 256 + threadIdx.x;  // < 49152
        int layer = i >= 24576;
        int j = i - layer * 24576;
        int col = j >> 6, k2 = j & 63;
        int cc = col & 127;
        const float* W;
        if (col < 128)      W = layer ? W2s : W1s;
        else if (col < 256) W = layer ? Wl2 : Wl1;
        else                W = layer ? W2d : W1d;
        g_Wp[i] = __floats2half2_rn(W[(2 * k2) * 128 + cc], W[(2 * k2 + 1) * 128 + cc]);
        if (i < 128) {
            g_biasA[i]       = bl1[i] + b1[i];
            g_biasA[128 + i] = bl2[i] + b2[i];
        }
    }
}

// ------------------------- software grid barrier -------------------------
__device__ __forceinline__ void gbar(int k)
{
    __syncthreads();
    if (threadIdx.x == 0) {
        __threadfence();
        int t = atomicAdd(&g_barc[k], 1);
        if (t == NBLK - 1) {
            g_barc[k] = 0;
            __threadfence();
            atomicExch(&g_barf[k], 1);
        } else {
            while (atomicAdd(&g_barf[k], 0) == 0) __nanosleep(64);
        }
        __threadfence();
    }
    __syncthreads();
}

// ------------------------- single-kernel CSR build -----------------------
__global__ __launch_bounds__(1024) void csr_all(const int* __restrict__ src,
                                                const int* __restrict__ dst,
                                                int E, int n)
{
    __shared__ int s[1024];
    __shared__ int sb[256];
    const int tid = threadIdx.x;
    const int gid = blockIdx.x * 1024 + tid;
    const int GT = NBLK * 1024;

    for (int i = gid; i < n; i += GT) g_cnt[i] = 0;
    gbar(0);
    for (int e = gid; e < E; e += GT) atomicAdd(&g_cnt[dst[e]], 1);
    gbar(1);
    const int CH = (n + NBLK - 1) / NBLK;
    const int base = blockIdx.x * CH;
    int myc = 0;
    if (tid < CH && base + tid < n) myc = g_cnt[base + tid];
    s[tid] = myc;
    __syncthreads();
    for (int off = 1; off < 1024; off <<= 1) {
        int v = (tid >= off) ? s[tid - off] : 0;
        __syncthreads();
        s[tid] += v;
        __syncthreads();
    }
    int myincl = s[tid];
    if (tid == 1023) g_bsum[blockIdx.x] = s[1023];
    gbar(2);
    if (tid < 256) sb[tid] = (tid < NBLK) ? g_bsum[tid] : 0;
    __syncthreads();
    for (int off = 1; off < 256; off <<= 1) {
        int v = 0;
        if (tid < 256 && tid >= off) v = sb[tid - off];
        __syncthreads();
        if (tid < 256) sb[tid] += v;
        __syncthreads();
    }
    int off0 = (blockIdx.x == 0) ? 0 : sb[blockIdx.x - 1];
    if (tid < CH && base + tid < n) {
        int v = off0 + myincl - myc;
        g_rowptr[base + tid] = v;
        g_woff[base + tid] = v;
    }
    if (blockIdx.x == 0 && tid == 0) g_rowptr[n] = E;
    gbar(3);
    for (int e = gid; e < E; e += GT) {
        int d = dst[e];
        int pz = atomicAdd(&g_woff[d], 1);
        g_csrc[pz] = src[e];
    }
}

// ------------------------- fp16 GEMM: K-resident, cp.async ---------------
#define SSTR 68   // half2 stride per row (64 + 4 pad)

__global__ __launch_bounds__(256) void gemm_h(const __half* __restrict__ Ah,
                                              float* __restrict__ acc,
                                              const __half2* __restrict__ Wp,
                                              const float* __restrict__ biasv,
                                              const float* __restrict__ att_s,
                                              const float* __restrict__ att_d,
                                              int M)
{
    extern __shared__ __half2 smp[];
    __half2* As = smp;                 // [128][SSTR]
    __half2* Bs = smp + 128 * SSTR;    // [128][SSTR]

    const int tid = threadIdx.x;
    const int lane = tid & 31;
    const int warp = tid >> 5;
    const int wm = warp >> 2;
    const int wn = warp & 3;
    const int row0 = blockIdx.x * 128;
    const int y = blockIdx.y;
    const int col0 = y * 128;
    const int g = lane >> 2;
    const int t4 = lane & 3;

    #pragma unroll
    for (int j = 0; j < 8; j++) {
        int idx = tid + j * 256;
        int row = idx >> 4, part = idx & 15;
        int grow = row0 + row;
        const __half* srcp = Ah + (size_t)(grow < M ? grow : 0) * 128 + part * 8;
        uint32_t dstu = smem_u32(&As[row * SSTR + part * 4]);
        CP_ASYNC16(dstu, srcp, (grow < M) ? 16 : 0);
    }
    #pragma unroll
    for (int j = 0; j < 8; j++) {
        int idx = tid + j * 256;
        int col = idx >> 4, part = idx & 15;
        const __half2* srcp = Wp + (size_t)(col0 + col) * 64 + part * 4;
        uint32_t dstu = smem_u32(&Bs[col * SSTR + part * 4]);
        CP_ASYNC16(dstu, srcp, 16);
    }
    asm volatile("cp.async.commit_group;");

    float c[4][4][4];
    #pragma unroll
    for (int i = 0; i < 4; i++)
        #pragma unroll
        for (int j = 0; j < 4; j++)
            #pragma unroll
            for (int q = 0; q < 4; q++) c[i][j][q] = 0.f;

    uint32_t a_base[4], b_base[2];
    {
        int ar = lane & 15;
        int kq = (lane >> 4) * 4;
        #pragma unroll
        for (int mt = 0; mt < 4; mt++)
            a_base[mt] = smem_u32(&As[(wm * 64 + mt * 16 + ar) * SSTR + kq]);
        int nr = (lane & 7) + ((lane >> 4) & 1) * 8;
        int kh = ((lane >> 3) & 1) * 4;
        b_base[0] = smem_u32(&Bs[(wn * 32 + nr) * SSTR + kh]);
        b_base[1] = smem_u32(&Bs[(wn * 32 + 16 + nr) * SSTR + kh]);
    }

    asm volatile("cp.async.wait_group 0;");
    __syncthreads();

    #pragma unroll
    for (int kk = 0; kk < 8; kk++) {
        uint32_t af[4][4], b0[4], b1[4];
        #pragma unroll
        for (int mt = 0; mt < 4; mt++)
            LDSM_X4(af[mt][0], af[mt][1], af[mt][2], af[mt][3], a_base[mt] + kk * 32);
        LDSM_X4(b0[0], b0[1], b0[2], b0[3], b_base[0] + kk * 32);
        LDSM_X4(b1[0], b1[1], b1[2], b1[3], b_base[1] + kk * 32);
        #pragma unroll
        for (int mt = 0; mt < 4; mt++) {
            MMA16816(c[mt][0], af[mt][0], af[mt][1], af[mt][2], af[mt][3], b0[0], b0[1]);
            MMA16816(c[mt][1], af[mt][0], af[mt][1], af[mt][2], af[mt][3], b0[2], b0[3]);
            MMA16816(c[mt][2], af[mt][0], af[mt][1], af[mt][2], af[mt][3], b1[0], b1[1]);
            MMA16816(c[mt][3], af[mt][0], af[mt][1], af[mt][2], af[mt][3], b1[2], b1[3]);
        }
    }

    const int l2 = t4 * 2;
    if (y == 1) {
        #pragma unroll
        for (int mt = 0; mt < 4; mt++) {
            #pragma unroll
            for (int nt = 0; nt < 4; nt++) {
                int r = row0 + wm * 64 + mt * 16 + g;
                int cc = wn * 32 + nt * 8 + l2;
                float2 b2 = *(const float2*)(biasv + cc);
                if (r < M)
                    *(float2*)(acc + (size_t)r * 128 + cc) =
                        make_float2(c[mt][nt][0] + b2.x, c[mt][nt][1] + b2.y);
                if (r + 8 < M)
                    *(float2*)(acc + (size_t)(r + 8) * 128 + cc) =
                        make_float2(c[mt][nt][2] + b2.x, c[mt][nt][3] + b2.y);
            }
        }
    } else {
        const float* att = (y == 0) ? att_s : att_d;
        float* adst = (y == 0) ? g_as : g_ad;
        float2 attv[4];
        #pragma unroll
        for (int nt = 0; nt < 4; nt++)
            attv[nt] = *(const float2*)(att + wn * 32 + nt * 8 + l2);

        #pragma unroll
        for (int mt = 0; mt < 4; mt++) {
            int r = row0 + wm * 64 + mt * 16 + g;
            float p0 = 0.f, p1 = 0.f;
            #pragma unroll
            for (int nt = 0; nt < 4; nt++) {
                p0 = fmaf(c[mt][nt][0], attv[nt].x, fmaf(c[mt][nt][1], attv[nt].y, p0));
                p1 = fmaf(c[mt][nt][2], attv[nt].x, fmaf(c[mt][nt][3], attv[nt].y, p1));
                if (y == 0) {
                    int cc = wn * 32 + nt * 8 + l2;
                    if (r < M)
                        *(half2*)(g_xs_h + (size_t)r * 128 + cc) =
                            __floats2half2_rn(c[mt][nt][0], c[mt][nt][1]);
                    if (r + 8 < M)
                        *(half2*)(g_xs_h + (size_t)(r + 8) * 128 + cc) =
                            __floats2half2_rn(c[mt][nt][2], c[mt][nt][3]);
                }
            }
            p0 += __shfl_xor_sync(0xFFFFFFFFu, p0, 1);
            p0 += __shfl_xor_sync(0xFFFFFFFFu, p0, 2);
            p1 += __shfl_xor_sync(0xFFFFFFFFu, p1, 1);
            p1 += __shfl_xor_sync(0xFFFFFFFFu, p1, 2);
            if ((lane & 3) == 0) {
                if (r < M)     adst[r * 4 + wn] = p0;
                if (r + 8 < M) adst[(r + 8) * 4 + wn] = p1;
            }
        }
    }
}

// ------------------------- fast exp (FMA pipe) ---------------------------
__device__ __forceinline__ float fast_exp(float x)
{
    float t  = fmaf(x, 1.4426950408889634f, 12582912.0f);
    int   i  = __float_as_int(t);
    float fi = t - 12582912.0f;
    float f  = fmaf(x, 1.4426950408889634f, -fi);
    float p  = 0.0013333558f;
    p = fmaf(p, f, 0.0096181291f);
    p = fmaf(p, f, 0.0555041087f);
    p = fmaf(p, f, 0.2402265070f);
    p = fmaf(p, f, 0.6931471806f);
    p = fmaf(p, f, 1.0f);
    return __int_as_float(__float_as_int(p) + (i << 23));
}

// ------------------------- fused edge softmax-SpMM (+LN) -----------------
// R10 structure: fp16 gather, 2 edges/iter (half-warp each, LDG.128).
template <bool DO_LN>
__global__ __launch_bounds__(256) void edge_fused(float* __restrict__ io,
                                                  const float* __restrict__ gamma,
                                                  const float* __restrict__ beta,
                                                  int n)
{
    __shared__ float4 s_w4[8][32];
    __shared__ int    s_src[8][32];
    const int wid = threadIdx.x >> 5;
    const int lane = threadIdx.x & 31;
    if (DO_LN && blockIdx.x == 0 && threadIdx.x < 4)
        g_barf[threadIdx.x] = 0;                       // reset csr grid-barrier flags
    int node = (blockIdx.x * blockDim.x + threadIdx.x) >> 5;
    if (node >= n) return;

    const int rs = g_rowptr[node], re = g_rowptr[node + 1];
    const float4 ad4 = *(const float4*)(g_ad + (size_t)node * 4);
    const int hh = (lane & 15) >> 2;
    const int feat = (lane & 15) * 8;

    float acc[8] = {0.f, 0.f, 0.f, 0.f, 0.f, 0.f, 0.f, 0.f};
    float4 den = make_float4(0.f, 0.f, 0.f, 0.f);

    for (int base = rs; base < re; base += 32) {
        int e = base + lane;
        int sreg = 0;
        float4 w4 = make_float4(0.f, 0.f, 0.f, 0.f);
        if (e < re) {
            sreg = g_csrc[e];
            float4 a = *(const float4*)(g_as + (size_t)sreg * 4);
            float vx = a.x + ad4.x, vy = a.y + ad4.y;
            float vz = a.z + ad4.z, vw = a.w + ad4.w;
            vx = vx > 0.f ? vx : LRELU * vx;
            vy = vy > 0.f ? vy : LRELU * vy;
            vz = vz > 0.f ? vz : LRELU * vz;
            vw = vw > 0.f ? vw : LRELU * vw;
            w4.x = fast_exp(vx); w4.y = fast_exp(vy);
            w4.z = fast_exp(vz); w4.w = fast_exp(vw);
        }
        float4 t = w4;
        #pragma unroll
        for (int m = 16; m >= 1; m >>= 1) {
            t.x += __shfl_xor_sync(0xFFFFFFFFu, t.x, m);
            t.y += __shfl_xor_sync(0xFFFFFFFFu, t.y, m);
            t.z += __shfl_xor_sync(0xFFFFFFFFu, t.z, m);
            t.w += __shfl_xor_sync(0xFFFFFFFFu, t.w, m);
        }
        den.x += t.x; den.y += t.y; den.z += t.z; den.w += t.w;
        s_w4[wid][lane] = w4;
        s_src[wid][lane] = sreg;
        __syncwarp();

        int cnt = min(32, re - base);
        int iters = (cnt + 1) >> 1;
        #pragma unroll 4
        for (int it = 0; it < iters; it++) {
            int jsel = 2 * it + (lane >> 4);
            int sj = s_src[wid][jsel];
            float wv = ((const float*)&s_w4[wid][jsel])[hh];
            uint4 raw = *(const uint4*)(g_xs_h + (size_t)sj * 128 + feat);
            float2 f0 = __half22float2(*(half2*)&raw.x);
            float2 f1 = __half22float2(*(half2*)&raw.y);
            float2 f2 = __half22float2(*(half2*)&raw.z);
            float2 f3 = __half22float2(*(half2*)&raw.w);
            acc[0] = fmaf(wv, f0.x, acc[0]); acc[1] = fmaf(wv, f0.y, acc[1]);
            acc[2] = fmaf(wv, f1.x, acc[2]); acc[3] = fmaf(wv, f1.y, acc[3]);
            acc[4] = fmaf(wv, f2.x, acc[4]); acc[5] = fmaf(wv, f2.y, acc[5]);
            acc[6] = fmaf(wv, f3.x, acc[6]); acc[7] = fmaf(wv, f3.y, acc[7]);
        }
        __syncwarp();
    }

    #pragma unroll
    for (int k = 0; k < 8; k++)
        acc[k] += __shfl_xor_sync(0xFFFFFFFFu, acc[k], 16);

    float dh = (hh < 2) ? (hh == 0 ? den.x : den.y) : (hh == 2 ? den.z : den.w);
    float inv = __fdividef(1.f, dh + 1e-16f);

    float4 i0 = *(const float4*)(io + (size_t)node * 128 + feat);
    float4 i1 = *(const float4*)(io + (size_t)node * 128 + feat + 4);
    float o[8];
    o[0] = fmaf(acc[0], inv, i0.x); o[1] = fmaf(acc[1], inv, i0.y);
    o[2] = fmaf(acc[2], inv, i0.z); o[3] = fmaf(acc[3], inv, i0.w);
    o[4] = fmaf(acc[4], inv, i1.x); o[5] = fmaf(acc[5], inv, i1.y);
    o[6] = fmaf(acc[6], inv, i1.z); o[7] = fmaf(acc[7], inv, i1.w);

    if (DO_LN) {
        float sum = 0.f, sq = 0.f;
        #pragma unroll
        for (int k = 0; k < 8; k++) { sum += o[k]; sq = fmaf(o[k], o[k], sq); }
        #pragma unroll
        for (int m = 1; m <= 16; m <<= 1) {
            sum += __shfl_xor_sync(0xFFFFFFFFu, sum, m);
            sq  += __shfl_xor_sync(0xFFFFFFFFu, sq, m);
        }
        float mean = sum * (1.f / 256.f);        // lanes duplicated x2
        float var  = sq * (1.f / 256.f) - mean * mean;
        float rstd = rsqrtf(var + LN_EPS);
        float4 ga = *(const float4*)(gamma + feat);
        float4 gb = *(const float4*)(gamma + feat + 4);
        float4 ba = *(const float4*)(beta + feat);
        float4 bb = *(const float4*)(beta + feat + 4);
        float r[8];
        r[0] = fmaxf(0.f, (o[0] - mean) * rstd * ga.x + ba.x);
        r[1] = fmaxf(0.f, (o[1] - mean) * rstd * ga.y + ba.y);
        r[2] = fmaxf(0.f, (o[2] - mean) * rstd * ga.z + ba.z);
        r[3] = fmaxf(0.f, (o[3] - mean) * rstd * ga.w + ba.w);
        r[4] = fmaxf(0.f, (o[4] - mean) * rstd * gb.x + bb.x);
        r[5] = fmaxf(0.f, (o[5] - mean) * rstd * gb.y + bb.y);
        r[6] = fmaxf(0.f, (o[6] - mean) * rstd * gb.z + bb.z);
        r[7] = fmaxf(0.f, (o[7] - mean) * rstd * gb.w + bb.w);
        // fp16-only output (fp32 copy was a dead store)
        if (lane < 16) {
            __half2 hh2[4];
            hh2[0] = __floats2half2_rn(r[0], r[1]);
            hh2[1] = __floats2half2_rn(r[2], r[3]);
            hh2[2] = __floats2half2_rn(r[4], r[5]);
            hh2[3] = __floats2half2_rn(r[6], r[7]);
            *(uint4*)(g_h_h + (size_t)node * 128 + feat) = *(uint4*)hh2;
        }
    } else {
        if (lane < 16) {
            *(float4*)(io + (size_t)node * 128 + feat)     = make_float4(o[0], o[1], o[2], o[3]);
            *(float4*)(io + (size_t)node * 128 + feat + 4) = make_float4(o[4], o[5], o[6], o[7]);
        }
    }
}

// ------------------------- driver ----------------------------------------
extern "C" void kernel_launch(void* const* d_in, const int* in_sizes, int n_in,
                              void* d_out, int out_size)
{
    const float* x        = (const float*)d_in[0];
    const int*   ei       = (const int*)  d_in[1];
    const float* W1_src   = (const float*)d_in[2];
    const float* W1_dst   = (const float*)d_in[3];
    const float* att1_src = (const float*)d_in[4];
    const float* att1_dst = (const float*)d_in[5];
    const float* b1       = (const float*)d_in[6];
    const float* Wl1      = (const float*)d_in[7];
    const float* bl1      = (const float*)d_in[8];
    const float* gamma    = (const float*)d_in[9];
    const float* beta     = (const float*)d_in[10];
    const float* W2_src   = (const float*)d_in[11];
    const float* W2_dst   = (const float*)d_in[12];
    const float* att2_src = (const float*)d_in[13];
    const float* att2_dst = (const float*)d_in[14];
    const float* b2       = (const float*)d_in[15];
    const float* Wl2      = (const float*)d_in[16];
    const float* bl2      = (const float*)d_in[17];
    float* out = (float*)d_out;

    const int n = NN;
    const int E = EE;
    const int* src = ei;
    const int* dst = ei + E;

    void* p;
    cudaGetSymbolAddress(&p, g_acc1);  float* acc1 = (float*)p;
    cudaGetSymbolAddress(&p, g_Wp);    __half2* wp = (__half2*)p;
    cudaGetSymbolAddress(&p, g_biasA); float* bias = (float*)p;
    cudaGetSymbolAddress(&p, g_x_h);   __half* xh = (__half*)p;
    cudaGetSymbolAddress(&p, g_h_h);   __half* hh = (__half*)p;

    const int SMEM = 2 * 128 * SSTR * 4;   // 69632 B
    cudaFuncSetAttribute(gemm_h, cudaFuncAttributeMaxDynamicSharedMemorySize, SMEM);

    // side stream + events for CSR overlap (created once; host objects only)
    static cudaStream_t s2 = nullptr;
    static cudaEvent_t ev_fork = nullptr, ev_join = nullptr;
    if (!s2) {
        cudaStreamCreateWithFlags(&s2, cudaStreamNonBlocking);
        cudaEventCreateWithFlags(&ev_fork, cudaEventDisableTiming);
        cudaEventCreateWithFlags(&ev_join, cudaEventDisableTiming);
    }

    dim3 gemm_grid((n + 127) / 128, 3);
    int node_blocks = (n * 32 + 255) / 256;

    // fork: csr_all runs concurrently with prep_all + gemm1
    cudaEventRecord(ev_fork, 0);
    cudaStreamWaitEvent(s2, ev_fork, 0);
    csr_all<<<NBLK, 1024, 0, s2>>>(src, dst, E, n);
    cudaEventRecord(ev_join, s2);

    prep_all<<<3317, 256>>>(x, W1_src, W1_dst, Wl1, bl1, b1,
                            W2_src, W2_dst, Wl2, bl2, b2);
    gemm_h<<<gemm_grid, 256, SMEM>>>(xh, acc1, wp, bias,
                                     att1_src, att1_dst, n);

    // join: edge_fused needs both CSR and gemm1 outputs
    cudaStreamWaitEvent(0, ev_join, 0);
    edge_fused<true><<<node_blocks, 256>>>(acc1, gamma, beta, n);
    gemm_h<<<gemm_grid, 256, SMEM>>>(hh, out, wp + 384 * 64, bias + 128,
                                     att2_src, att2_dst, n);
    edge_fused<false><<<node_blocks, 256>>>(out, nullptr, nullptr, n);
}

// round 13
// speedup vs baseline: 1.1397x; 1.0447x over previous
#include <cuda_runtime.h>
#include <cuda_bf16.h>
#include <cuda_fp16.h>
#include <cstdint>

#define NN 50000
#define EE 800000
#define LRELU 0.2f
#define LN_EPS 1e-5f
#define NBLK 148

// ------------------------- scratch (device globals) ----------------------
__device__ __align__(16) __half g_x_h[(size_t)NN * 128];    // fp16 input x
__device__ __align__(16) __half g_h_h[(size_t)NN * 128];    // fp16 layer1 out
__device__ __align__(16) __half g_xs_h[(size_t)NN * 128];   // fp16 xs
__device__ float g_acc1[(size_t)NN * 128];
__device__ float g_as[NN * 4];
__device__ float g_ad[NN * 4];
__device__ __align__(16) __half2 g_Wp[2 * 384 * 64];   // [layer][col 384][k2 64] n-major
__device__ float g_biasA[2 * 128];
// CSR
__device__ int g_cnt[NN];
__device__ int g_rowptr[NN + 1];
__device__ int g_woff[NN];
__device__ int g_csrc[EE];
__device__ int g_bsum[NBLK];
// software grid barrier state
__device__ int g_barc[4];
__device__ int g_barf[4];

// ------------------------- helpers ---------------------------------------
__device__ __forceinline__ uint32_t smem_u32(const void* p)
{
    return (uint32_t)__cvta_generic_to_shared(p);
}

#define LDSM_X4(d0, d1, d2, d3, addr)                                            \
    asm volatile("ldmatrix.sync.aligned.m8n8.x4.shared.b16 {%0,%1,%2,%3}, [%4];" \
                 : "=r"(d0), "=r"(d1), "=r"(d2), "=r"(d3) : "r"(addr))

#define MMA16816(C, A0, A1, A2, A3, B0, B1)                                  \
    asm volatile("mma.sync.aligned.m16n8k16.row.col.f32.f16.f16.f32 "        \
                 "{%0,%1,%2,%3}, {%4,%5,%6,%7}, {%8,%9}, {%0,%1,%2,%3};"     \
                 : "+f"((C)[0]), "+f"((C)[1]), "+f"((C)[2]), "+f"((C)[3])    \
                 : "r"(A0), "r"(A1), "r"(A2), "r"(A3), "r"(B0), "r"(B1))

#define CP_ASYNC16(dst, src, sz)                                             \
    asm volatile("cp.async.cg.shared.global [%0], [%1], 16, %2;"             \
                 :: "r"(dst), "l"(src), "r"(sz))

// ------------------------- merged prep: x->fp16 + weight pack ------------
__global__ void prep_all(const float* __restrict__ X,
                         const float* __restrict__ W1s, const float* __restrict__ W1d,
                         const float* __restrict__ Wl1, const float* __restrict__ bl1,
                         const float* __restrict__ b1,
                         const float* __restrict__ W2s, const float* __restrict__ W2d,
                         const float* __restrict__ Wl2, const float* __restrict__ bl2,
                         const float* __restrict__ b2)
{
    if (blockIdx.x < 3125) {
        int i = blockIdx.x * 256 + threadIdx.x;           // < 800000 = NN*16
        const float4* p = (const float4*)X + (size_t)i * 2;
        float4 a = p[0], b = p[1];
        __half2 h[4];
        h[0] = __floats2half2_rn(a.x, a.y); h[1] = __floats2half2_rn(a.z, a.w);
        h[2] = __floats2half2_rn(b.x, b.y); h[3] = __floats2half2_rn(b.z, b.w);
        *(uint4*)(g_x_h + (size_t)i * 8) = *(uint4*)h;
    } else {
        int i = (blockIdx.x - 3125) * 256 + threadIdx.x;  // < 49152
        int layer = i >= 24576;
        int j = i - layer * 24576;
        int col = j >> 6, k2 = j & 63;
        int cc = col & 127;
        const float* W;
        if (col < 128)      W = layer ? W2s : W1s;
        else if (col < 256) W = layer ? Wl2 : Wl1;
        else                W = layer ? W2d : W1d;
        g_Wp[i] = __floats2half2_rn(W[(2 * k2) * 128 + cc], W[(2 * k2 + 1) * 128 + cc]);
        if (i < 128) {
            g_biasA[i]       = bl1[i] + b1[i];
            g_biasA[128 + i] = bl2[i] + b2[i];
        }
    }
}

// ------------------------- software grid barrier -------------------------
__device__ __forceinline__ void gbar(int k)
{
    __syncthreads();
    if (threadIdx.x == 0) {
        __threadfence();
        int t = atomicAdd(&g_barc[k], 1);
        if (t == NBLK - 1) {
            g_barc[k] = 0;
            __threadfence();
            atomicExch(&g_barf[k], 1);
        } else {
            while (atomicAdd(&g_barf[k], 0) == 0) __nanosleep(64);
        }
        __threadfence();
    }
    __syncthreads();
}

// ------------------------- single-kernel CSR build -----------------------
__global__ __launch_bounds__(1024) void csr_all(const int* __restrict__ src,
                                                const int* __restrict__ dst,
                                                int E, int n)
{
    __shared__ int s[1024];
    __shared__ int sb[256];
    const int tid = threadIdx.x;
    const int gid = blockIdx.x * 1024 + tid;
    const int GT = NBLK * 1024;

    for (int i = gid; i < n; i += GT) g_cnt[i] = 0;
    gbar(0);
    for (int e = gid; e < E; e += GT) atomicAdd(&g_cnt[dst[e]], 1);
    gbar(1);
    const int CH = (n + NBLK - 1) / NBLK;
    const int base = blockIdx.x * CH;
    int myc = 0;
    if (tid < CH && base + tid < n) myc = g_cnt[base + tid];
    s[tid] = myc;
    __syncthreads();
    for (int off = 1; off < 1024; off <<= 1) {
        int v = (tid >= off) ? s[tid - off] : 0;
        __syncthreads();
        s[tid] += v;
        __syncthreads();
    }
    int myincl = s[tid];
    if (tid == 1023) g_bsum[blockIdx.x] = s[1023];
    gbar(2);
    if (tid < 256) sb[tid] = (tid < NBLK) ? g_bsum[tid] : 0;
    __syncthreads();
    for (int off = 1; off < 256; off <<= 1) {
        int v = 0;
        if (tid < 256 && tid >= off) v = sb[tid - off];
        __syncthreads();
        if (tid < 256) sb[tid] += v;
        __syncthreads();
    }
    int off0 = (blockIdx.x == 0) ? 0 : sb[blockIdx.x - 1];
    if (tid < CH && base + tid < n) {
        int v = off0 + myincl - myc;
        g_rowptr[base + tid] = v;
        g_woff[base + tid] = v;
    }
    if (blockIdx.x == 0 && tid == 0) g_rowptr[n] = E;
    gbar(3);
    for (int e = gid; e < E; e += GT) {
        int d = dst[e];
        int pz = atomicAdd(&g_woff[d], 1);
        g_csrc[pz] = src[e];
    }
}

// ------------------------- fp16 GEMM: K-resident, swizzled (2 CTA/SM) ----
// 16B-granule XOR swizzle: granule' = granule ^ (row & 7). 64KB smem exact.
__global__ __launch_bounds__(256, 2) void gemm_h(const __half* __restrict__ Ah,
                                                 float* __restrict__ acc,
                                                 const __half2* __restrict__ Wp,
                                                 const float* __restrict__ biasv,
                                                 const float* __restrict__ att_s,
                                                 const float* __restrict__ att_d,
                                                 int M)
{
    extern __shared__ __half2 smp[];
    __half2* As = smp;                 // [128][64] half2, swizzled granules
    __half2* Bs = smp + 128 * 64;

    const int tid = threadIdx.x;
    const int lane = tid & 31;
    const int warp = tid >> 5;
    const int wm = warp >> 2;
    const int wn = warp & 3;
    const int row0 = blockIdx.x * 128;
    const int y = blockIdx.y;
    const int col0 = y * 128;
    const int g = lane >> 2;
    const int t4 = lane & 3;

    // bulk async loads with swizzled destination granules
    #pragma unroll
    for (int j = 0; j < 8; j++) {
        int idx = tid + j * 256;
        int row = idx >> 4, part = idx & 15;
        int grow = row0 + row;
        const __half* srcp = Ah + (size_t)(grow < M ? grow : 0) * 128 + part * 8;
        uint32_t dstu = smem_u32(&As[row * 64 + (part ^ (row & 7)) * 4]);
        CP_ASYNC16(dstu, srcp, (grow < M) ? 16 : 0);
    }
    #pragma unroll
    for (int j = 0; j < 8; j++) {
        int idx = tid + j * 256;
        int col = idx >> 4, part = idx & 15;
        const __half2* srcp = Wp + (size_t)(col0 + col) * 64 + part * 4;
        uint32_t dstu = smem_u32(&Bs[col * 64 + (part ^ (col & 7)) * 4]);
        CP_ASYNC16(dstu, srcp, 16);
    }
    asm volatile("cp.async.commit_group;");

    float c[4][4][4];
    #pragma unroll
    for (int i = 0; i < 4; i++)
        #pragma unroll
        for (int j = 0; j < 4; j++)
            #pragma unroll
            for (int q = 0; q < 4; q++) c[i][j][q] = 0.f;

    // row base pointers (swizzle applied per-kk below)
    uint32_t aptr[4], bptr[2];
    const int ar = lane & 15;
    const int amask = ar & 7;
    #pragma unroll
    for (int mt = 0; mt < 4; mt++)
        aptr[mt] = smem_u32(&As[(wm * 64 + mt * 16 + ar) * 64]);
    const int nr = (lane & 7) + ((lane >> 4) & 1) * 8;
    const int bmask = lane & 7;        // (nr & 7) == (lane & 7), also for nr+16
    bptr[0] = smem_u32(&Bs[(wn * 32 + nr) * 64]);
    bptr[1] = smem_u32(&Bs[(wn * 32 + 16 + nr) * 64]);
    const int agq = lane >> 4;         // A granule sub-index
    const int bgq = (lane >> 3) & 1;   // B granule sub-index

    asm volatile("cp.async.wait_group 0;");
    __syncthreads();

    #pragma unroll
    for (int kk = 0; kk < 8; kk++) {
        uint32_t gA = (uint32_t)(((kk * 2 + agq) ^ amask) * 16);
        uint32_t gB = (uint32_t)(((kk * 2 + bgq) ^ bmask) * 16);
        uint32_t af[4][4], b0[4], b1[4];
        #pragma unroll
        for (int mt = 0; mt < 4; mt++)
            LDSM_X4(af[mt][0], af[mt][1], af[mt][2], af[mt][3], aptr[mt] + gA);
        LDSM_X4(b0[0], b0[1], b0[2], b0[3], bptr[0] + gB);
        LDSM_X4(b1[0], b1[1], b1[2], b1[3], bptr[1] + gB);
        #pragma unroll
        for (int mt = 0; mt < 4; mt++) {
            MMA16816(c[mt][0], af[mt][0], af[mt][1], af[mt][2], af[mt][3], b0[0], b0[1]);
            MMA16816(c[mt][1], af[mt][0], af[mt][1], af[mt][2], af[mt][3], b0[2], b0[3]);
            MMA16816(c[mt][2], af[mt][0], af[mt][1], af[mt][2], af[mt][3], b1[0], b1[1]);
            MMA16816(c[mt][3], af[mt][0], af[mt][1], af[mt][2], af[mt][3], b1[2], b1[3]);
        }
    }

    const int l2 = t4 * 2;
    if (y == 1) {
        #pragma unroll
        for (int mt = 0; mt < 4; mt++) {
            #pragma unroll
            for (int nt = 0; nt < 4; nt++) {
                int r = row0 + wm * 64 + mt * 16 + g;
                int cc = wn * 32 + nt * 8 + l2;
                float2 b2 = *(const float2*)(biasv + cc);
                if (r < M)
                    *(float2*)(acc + (size_t)r * 128 + cc) =
                        make_float2(c[mt][nt][0] + b2.x, c[mt][nt][1] + b2.y);
                if (r + 8 < M)
                    *(float2*)(acc + (size_t)(r + 8) * 128 + cc) =
                        make_float2(c[mt][nt][2] + b2.x, c[mt][nt][3] + b2.y);
            }
        }
    } else {
        const float* att = (y == 0) ? att_s : att_d;
        float* adst = (y == 0) ? g_as : g_ad;
        float2 attv[4];
        #pragma unroll
        for (int nt = 0; nt < 4; nt++)
            attv[nt] = *(const float2*)(att + wn * 32 + nt * 8 + l2);

        #pragma unroll
        for (int mt = 0; mt < 4; mt++) {
            int r = row0 + wm * 64 + mt * 16 + g;
            float p0 = 0.f, p1 = 0.f;
            #pragma unroll
            for (int nt = 0; nt < 4; nt++) {
                p0 = fmaf(c[mt][nt][0], attv[nt].x, fmaf(c[mt][nt][1], attv[nt].y, p0));
                p1 = fmaf(c[mt][nt][2], attv[nt].x, fmaf(c[mt][nt][3], attv[nt].y, p1));
                if (y == 0) {
                    int cc = wn * 32 + nt * 8 + l2;
                    if (r < M)
                        *(half2*)(g_xs_h + (size_t)r * 128 + cc) =
                            __floats2half2_rn(c[mt][nt][0], c[mt][nt][1]);
                    if (r + 8 < M)
                        *(half2*)(g_xs_h + (size_t)(r + 8) * 128 + cc) =
                            __floats2half2_rn(c[mt][nt][2], c[mt][nt][3]);
                }
            }
            p0 += __shfl_xor_sync(0xFFFFFFFFu, p0, 1);
            p0 += __shfl_xor_sync(0xFFFFFFFFu, p0, 2);
            p1 += __shfl_xor_sync(0xFFFFFFFFu, p1, 1);
            p1 += __shfl_xor_sync(0xFFFFFFFFu, p1, 2);
            if ((lane & 3) == 0) {
                if (r < M)     adst[r * 4 + wn] = p0;
                if (r + 8 < M) adst[(r + 8) * 4 + wn] = p1;
            }
        }
    }
}

// ------------------------- fused edge softmax-SpMM (+LN) -----------------
// fp16 gather, 2 edges/iter; exp via MUFU; den reduced once per node.
template <bool DO_LN>
__global__ __launch_bounds__(256) void edge_fused(float* __restrict__ io,
                                                  const float* __restrict__ gamma,
                                                  const float* __restrict__ beta,
                                                  int n)
{
    __shared__ float4 s_w4[8][32];
    __shared__ int    s_src[8][32];
    const int wid = threadIdx.x >> 5;
    const int lane = threadIdx.x & 31;
    if (DO_LN && blockIdx.x == 0 && threadIdx.x < 4)
        g_barf[threadIdx.x] = 0;                       // reset csr grid-barrier flags
    int node = (blockIdx.x * blockDim.x + threadIdx.x) >> 5;
    if (node >= n) return;

    const int rs = g_rowptr[node], re = g_rowptr[node + 1];
    const float4 ad4 = *(const float4*)(g_ad + (size_t)node * 4);
    const int hh = (lane & 15) >> 2;
    const int feat = (lane & 15) * 8;

    float acc[8] = {0.f, 0.f, 0.f, 0.f, 0.f, 0.f, 0.f, 0.f};
    float4 wsum = make_float4(0.f, 0.f, 0.f, 0.f);     // per-lane; reduced after loop

    for (int base = rs; base < re; base += 32) {
        int e = base + lane;
        int sreg = 0;
        float4 w4 = make_float4(0.f, 0.f, 0.f, 0.f);
        if (e < re) {
            sreg = g_csrc[e];
            float4 a = *(const float4*)(g_as + (size_t)sreg * 4);
            float vx = a.x + ad4.x, vy = a.y + ad4.y;
            float vz = a.z + ad4.z, vw = a.w + ad4.w;
            vx = vx > 0.f ? vx : LRELU * vx;
            vy = vy > 0.f ? vy : LRELU * vy;
            vz = vz > 0.f ? vz : LRELU * vz;
            vw = vw > 0.f ? vw : LRELU * vw;
            w4.x = __expf(vx); w4.y = __expf(vy);
            w4.z = __expf(vz); w4.w = __expf(vw);
        }
        wsum.x += w4.x; wsum.y += w4.y; wsum.z += w4.z; wsum.w += w4.w;
        s_w4[wid][lane] = w4;
        s_src[wid][lane] = sreg;
        __syncwarp();

        int cnt = min(32, re - base);
        int iters = (cnt + 1) >> 1;
        #pragma unroll 4
        for (int it = 0; it < iters; it++) {
            int jsel = 2 * it + (lane >> 4);
            int sj = s_src[wid][jsel];
            float wv = ((const float*)&s_w4[wid][jsel])[hh];
            uint4 raw = *(const uint4*)(g_xs_h + (size_t)sj * 128 + feat);
            float2 f0 = __half22float2(*(half2*)&raw.x);
            float2 f1 = __half22float2(*(half2*)&raw.y);
            float2 f2 = __half22float2(*(half2*)&raw.z);
            float2 f3 = __half22float2(*(half2*)&raw.w);
            acc[0] = fmaf(wv, f0.x, acc[0]); acc[1] = fmaf(wv, f0.y, acc[1]);
            acc[2] = fmaf(wv, f1.x, acc[2]); acc[3] = fmaf(wv, f1.y, acc[3]);
            acc[4] = fmaf(wv, f2.x, acc[4]); acc[5] = fmaf(wv, f2.y, acc[5]);
            acc[6] = fmaf(wv, f3.x, acc[6]); acc[7] = fmaf(wv, f3.y, acc[7]);
        }
        __syncwarp();
    }

    #pragma unroll
    for (int k = 0; k < 8; k++)
        acc[k] += __shfl_xor_sync(0xFFFFFFFFu, acc[k], 16);

    // single denominator reduce per node
    #pragma unroll
    for (int m = 16; m >= 1; m >>= 1) {
        wsum.x += __shfl_xor_sync(0xFFFFFFFFu, wsum.x, m);
        wsum.y += __shfl_xor_sync(0xFFFFFFFFu, wsum.y, m);
        wsum.z += __shfl_xor_sync(0xFFFFFFFFu, wsum.z, m);
        wsum.w += __shfl_xor_sync(0xFFFFFFFFu, wsum.w, m);
    }
    float dh = (hh < 2) ? (hh == 0 ? wsum.x : wsum.y) : (hh == 2 ? wsum.z : wsum.w);
    float inv = __fdividef(1.f, dh + 1e-16f);

    float4 i0 = *(const float4*)(io + (size_t)node * 128 + feat);
    float4 i1 = *(const float4*)(io + (size_t)node * 128 + feat + 4);
    float o[8];
    o[0] = fmaf(acc[0], inv, i0.x); o[1] = fmaf(acc[1], inv, i0.y);
    o[2] = fmaf(acc[2], inv, i0.z); o[3] = fmaf(acc[3], inv, i0.w);
    o[4] = fmaf(acc[4], inv, i1.x); o[5] = fmaf(acc[5], inv, i1.y);
    o[6] = fmaf(acc[6], inv, i1.z); o[7] = fmaf(acc[7], inv, i1.w);

    if (DO_LN) {
        float sum = 0.f, sq = 0.f;
        #pragma unroll
        for (int k = 0; k < 8; k++) { sum += o[k]; sq = fmaf(o[k], o[k], sq); }
        #pragma unroll
        for (int m = 1; m <= 16; m <<= 1) {
            sum += __shfl_xor_sync(0xFFFFFFFFu, sum, m);
            sq  += __shfl_xor_sync(0xFFFFFFFFu, sq, m);
        }
        float mean = sum * (1.f / 256.f);        // lanes duplicated x2
        float var  = sq * (1.f / 256.f) - mean * mean;
        float rstd = rsqrtf(var + LN_EPS);
        float4 ga = *(const float4*)(gamma + feat);
        float4 gb = *(const float4*)(gamma + feat + 4);
        float4 ba = *(const float4*)(beta + feat);
        float4 bb = *(const float4*)(beta + feat + 4);
        float r[8];
        r[0] = fmaxf(0.f, (o[0] - mean) * rstd * ga.x + ba.x);
        r[1] = fmaxf(0.f, (o[1] - mean) * rstd * ga.y + ba.y);
        r[2] = fmaxf(0.f, (o[2] - mean) * rstd * ga.z + ba.z);
        r[3] = fmaxf(0.f, (o[3] - mean) * rstd * ga.w + ba.w);
        r[4] = fmaxf(0.f, (o[4] - mean) * rstd * gb.x + bb.x);
        r[5] = fmaxf(0.f, (o[5] - mean) * rstd * gb.y + bb.y);
        r[6] = fmaxf(0.f, (o[6] - mean) * rstd * gb.z + bb.z);
        r[7] = fmaxf(0.f, (o[7] - mean) * rstd * gb.w + bb.w);
        if (lane < 16) {
            __half2 hh2[4];
            hh2[0] = __floats2half2_rn(r[0], r[1]);
            hh2[1] = __floats2half2_rn(r[2], r[3]);
            hh2[2] = __floats2half2_rn(r[4], r[5]);
            hh2[3] = __floats2half2_rn(r[6], r[7]);
            *(uint4*)(g_h_h + (size_t)node * 128 + feat) = *(uint4*)hh2;
        }
    } else {
        if (lane < 16) {
            *(float4*)(io + (size_t)node * 128 + feat)     = make_float4(o[0], o[1], o[2], o[3]);
            *(float4*)(io + (size_t)node * 128 + feat + 4) = make_float4(o[4], o[5], o[6], o[7]);
        }
    }
}

// ------------------------- driver ----------------------------------------
extern "C" void kernel_launch(void* const* d_in, const int* in_sizes, int n_in,
                              void* d_out, int out_size)
{
    const float* x        = (const float*)d_in[0];
    const int*   ei       = (const int*)  d_in[1];
    const float* W1_src   = (const float*)d_in[2];
    const float* W1_dst   = (const float*)d_in[3];
    const float* att1_src = (const float*)d_in[4];
    const float* att1_dst = (const float*)d_in[5];
    const float* b1       = (const float*)d_in[6];
    const float* Wl1      = (const float*)d_in[7];
    const float* bl1      = (const float*)d_in[8];
    const float* gamma    = (const float*)d_in[9];
    const float* beta     = (const float*)d_in[10];
    const float* W2_src   = (const float*)d_in[11];
    const float* W2_dst   = (const float*)d_in[12];
    const float* att2_src = (const float*)d_in[13];
    const float* att2_dst = (const float*)d_in[14];
    const float* b2       = (const float*)d_in[15];
    const float* Wl2      = (const float*)d_in[16];
    const float* bl2      = (const float*)d_in[17];
    float* out = (float*)d_out;

    const int n = NN;
    const int E = EE;
    const int* src = ei;
    const int* dst = ei + E;

    void* p;
    cudaGetSymbolAddress(&p, g_acc1);  float* acc1 = (float*)p;
    cudaGetSymbolAddress(&p, g_Wp);    __half2* wp = (__half2*)p;
    cudaGetSymbolAddress(&p, g_biasA); float* bias = (float*)p;
    cudaGetSymbolAddress(&p, g_x_h);   __half* xh = (__half*)p;
    cudaGetSymbolAddress(&p, g_h_h);   __half* hh = (__half*)p;

    const int SMEM = 2 * 128 * 64 * 4;   // 65536 B exact -> 2 CTAs/SM
    cudaFuncSetAttribute(gemm_h, cudaFuncAttributeMaxDynamicSharedMemorySize, SMEM);

    static cudaStream_t s2 = nullptr;
    static cudaEvent_t ev_fork = nullptr, ev_join = nullptr;
    if (!s2) {
        cudaStreamCreateWithFlags(&s2, cudaStreamNonBlocking);
        cudaEventCreateWithFlags(&ev_fork, cudaEventDisableTiming);
        cudaEventCreateWithFlags(&ev_join, cudaEventDisableTiming);
    }

    dim3 gemm_grid((n + 127) / 128, 3);
    int node_blocks = (n * 32 + 255) / 256;

    // fork: csr_all runs concurrently with prep_all + gemm1
    cudaEventRecord(ev_fork, 0);
    cudaStreamWaitEvent(s2, ev_fork, 0);
    csr_all<<<NBLK, 1024, 0, s2>>>(src, dst, E, n);
    cudaEventRecord(ev_join, s2);

    prep_all<<<3317, 256>>>(x, W1_src, W1_dst, Wl1, bl1, b1,
                            W2_src, W2_dst, Wl2, bl2, b2);
    gemm_h<<<gemm_grid, 256, SMEM>>>(xh, acc1, wp, bias,
                                     att1_src, att1_dst, n);

    cudaStreamWaitEvent(0, ev_join, 0);
    edge_fused<true><<<node_blocks, 256>>>(acc1, gamma, beta, n);
    gemm_h<<<gemm_grid, 256, SMEM>>>(hh, out, wp + 384 * 64, bias + 128,
                                     att2_src, att2_dst, n);
    edge_fused<false><<<node_blocks, 256>>>(out, nullptr, nullptr, n);
}

// round 15
// speedup vs baseline: 1.1895x; 1.0438x over previous
#include <cuda_runtime.h>
#include <cuda_bf16.h>
#include <cuda_fp16.h>
#include <cstdint>

#define NN 50000
#define EE 800000
#define LRELU 0.2f
#define LN_EPS 1e-5f
#define NBLK 148

// ------------------------- scratch (device globals) ----------------------
__device__ __align__(16) __half g_x_h[(size_t)NN * 128];    // fp16 input x
__device__ __align__(16) __half g_h_h[(size_t)NN * 128];    // fp16 layer1 out
__device__ __align__(16) __half g_xs_h[(size_t)NN * 128];   // fp16 xs
__device__ float g_acc1[(size_t)NN * 128];
__device__ float g_as[NN * 4];
__device__ float g_ad[NN * 4];
__device__ __align__(16) __half2 g_Wp[2 * 384 * 64];   // [layer][col 384][k2 64] n-major
__device__ float g_biasA[2 * 128];
// CSR
__device__ int g_cnt[NN];
__device__ int g_rowptr[NN + 1];
__device__ int g_woff[NN];
__device__ int g_csrc[EE];
__device__ int g_bsum[NBLK];
// software grid barrier state
__device__ int g_barc[4];
__device__ int g_barf[4];

// ------------------------- helpers ---------------------------------------
__device__ __forceinline__ uint32_t smem_u32(const void* p)
{
    return (uint32_t)__cvta_generic_to_shared(p);
}

#define LDSM_X4(d0, d1, d2, d3, addr)                                            \
    asm volatile("ldmatrix.sync.aligned.m8n8.x4.shared.b16 {%0,%1,%2,%3}, [%4];" \
                 : "=r"(d0), "=r"(d1), "=r"(d2), "=r"(d3) : "r"(addr))

#define MMA16816(C, A0, A1, A2, A3, B0, B1)                                  \
    asm volatile("mma.sync.aligned.m16n8k16.row.col.f32.f16.f16.f32 "        \
                 "{%0,%1,%2,%3}, {%4,%5,%6,%7}, {%8,%9}, {%0,%1,%2,%3};"     \
                 : "+f"((C)[0]), "+f"((C)[1]), "+f"((C)[2]), "+f"((C)[3])    \
                 : "r"(A0), "r"(A1), "r"(A2), "r"(A3), "r"(B0), "r"(B1))

#define CP_ASYNC16(dst, src, sz)                                             \
    asm volatile("cp.async.cg.shared.global [%0], [%1], 16, %2;"             \
                 :: "r"(dst), "l"(src), "r"(sz))

// ------------------------- merged prep: x->fp16 + weight pack ------------
__global__ void prep_all(const float* __restrict__ X,
                         const float* __restrict__ W1s, const float* __restrict__ W1d,
                         const float* __restrict__ Wl1, const float* __restrict__ bl1,
                         const float* __restrict__ b1,
                         const float* __restrict__ W2s, const float* __restrict__ W2d,
                         const float* __restrict__ Wl2, const float* __restrict__ bl2,
                         const float* __restrict__ b2)
{
    if (blockIdx.x < 3125) {
        int i = blockIdx.x * 256 + threadIdx.x;           // < 800000 = NN*16
        const float4* p = (const float4*)X + (size_t)i * 2;
        float4 a = p[0], b = p[1];
        __half2 h[4];
        h[0] = __floats2half2_rn(a.x, a.y); h[1] = __floats2half2_rn(a.z, a.w);
        h[2] = __floats2half2_rn(b.x, b.y); h[3] = __floats2half2_rn(b.z, b.w);
        *(uint4*)(g_x_h + (size_t)i * 8) = *(uint4*)h;
    } else {
        int i = (blockIdx.x - 3125) * 256 + threadIdx.x;  // < 49152
        int layer = i >= 24576;
        int j = i - layer * 24576;
        int col = j >> 6, k2 = j & 63;
        int cc = col & 127;
        const float* W;
        if (col < 128)      W = layer ? W2s : W1s;
        else if (col < 256) W = layer ? Wl2 : Wl1;
        else                W = layer ? W2d : W1d;
        g_Wp[i] = __floats2half2_rn(W[(2 * k2) * 128 + cc], W[(2 * k2 + 1) * 128 + cc]);
        if (i < 128) {
            g_biasA[i]       = bl1[i] + b1[i];
            g_biasA[128 + i] = bl2[i] + b2[i];
        }
    }
}

// ------------------------- software grid barrier -------------------------
__device__ __forceinline__ void gbar(int k)
{
    __syncthreads();
    if (threadIdx.x == 0) {
        __threadfence();
        int t = atomicAdd(&g_barc[k], 1);
        if (t == NBLK - 1) {
            g_barc[k] = 0;
            __threadfence();
            atomicExch(&g_barf[k], 1);
        } else {
            while (atomicAdd(&g_barf[k], 0) == 0) __nanosleep(64);
        }
        __threadfence();
    }
    __syncthreads();
}

// ------------------------- single-kernel CSR build -----------------------
__global__ __launch_bounds__(1024) void csr_all(const int* __restrict__ src,
                                                const int* __restrict__ dst,
                                                int E, int n)
{
    __shared__ int s[1024];
    __shared__ int sb[256];
    const int tid = threadIdx.x;
    const int gid = blockIdx.x * 1024 + tid;
    const int GT = NBLK * 1024;

    for (int i = gid; i < n; i += GT) g_cnt[i] = 0;
    gbar(0);
    for (int e = gid; e < E; e += GT) atomicAdd(&g_cnt[dst[e]], 1);
    gbar(1);
    const int CH = (n + NBLK - 1) / NBLK;
    const int base = blockIdx.x * CH;
    int myc = 0;
    if (tid < CH && base + tid < n) myc = g_cnt[base + tid];
    s[tid] = myc;
    __syncthreads();
    for (int off = 1; off < 1024; off <<= 1) {
        int v = (tid >= off) ? s[tid - off] : 0;
        __syncthreads();
        s[tid] += v;
        __syncthreads();
    }
    int myincl = s[tid];
    if (tid == 1023) g_bsum[blockIdx.x] = s[1023];
    gbar(2);
    if (tid < 256) sb[tid] = (tid < NBLK) ? g_bsum[tid] : 0;
    __syncthreads();
    for (int off = 1; off < 256; off <<= 1) {
        int v = 0;
        if (tid < 256 && tid >= off) v = sb[tid - off];
        __syncthreads();
        if (tid < 256) sb[tid] += v;
        __syncthreads();
    }
    int off0 = (blockIdx.x == 0) ? 0 : sb[blockIdx.x - 1];
    if (tid < CH && base + tid < n) {
        int v = off0 + myincl - myc;
        g_rowptr[base + tid] = v;
        g_woff[base + tid] = v;
    }
    if (blockIdx.x == 0 && tid == 0) g_rowptr[n] = E;
    gbar(3);
    for (int e = gid; e < E; e += GT) {
        int d = dst[e];
        int pz = atomicAdd(&g_woff[d], 1);
        g_csrc[pz] = src[e];
    }
}

// ------------------------- fp16 GEMM: K-resident, swizzled (2 CTA/SM) ----
__global__ __launch_bounds__(256, 2) void gemm_h(const __half* __restrict__ Ah,
                                                 float* __restrict__ acc,
                                                 const __half2* __restrict__ Wp,
                                                 const float* __restrict__ biasv,
                                                 const float* __restrict__ att_s,
                                                 const float* __restrict__ att_d,
                                                 int M)
{
    extern __shared__ __half2 smp[];
    __half2* As = smp;                 // [128][64] half2, swizzled granules
    __half2* Bs = smp + 128 * 64;

    const int tid = threadIdx.x;
    const int lane = tid & 31;
    const int warp = tid >> 5;
    const int wm = warp >> 2;
    const int wn = warp & 3;
    const int row0 = blockIdx.x * 128;
    const int y = blockIdx.y;
    const int col0 = y * 128;
    const int g = lane >> 2;
    const int t4 = lane & 3;

    #pragma unroll
    for (int j = 0; j < 8; j++) {
        int idx = tid + j * 256;
        int row = idx >> 4, part = idx & 15;
        int grow = row0 + row;
        const __half* srcp = Ah + (size_t)(grow < M ? grow : 0) * 128 + part * 8;
        uint32_t dstu = smem_u32(&As[row * 64 + (part ^ (row & 7)) * 4]);
        CP_ASYNC16(dstu, srcp, (grow < M) ? 16 : 0);
    }
    #pragma unroll
    for (int j = 0; j < 8; j++) {
        int idx = tid + j * 256;
        int col = idx >> 4, part = idx & 15;
        const __half2* srcp = Wp + (size_t)(col0 + col) * 64 + part * 4;
        uint32_t dstu = smem_u32(&Bs[col * 64 + (part ^ (col & 7)) * 4]);
        CP_ASYNC16(dstu, srcp, 16);
    }
    asm volatile("cp.async.commit_group;");

    float c[4][4][4];
    #pragma unroll
    for (int i = 0; i < 4; i++)
        #pragma unroll
        for (int j = 0; j < 4; j++)
            #pragma unroll
            for (int q = 0; q < 4; q++) c[i][j][q] = 0.f;

    uint32_t aptr[4], bptr[2];
    const int ar = lane & 15;
    const int amask = ar & 7;
    #pragma unroll
    for (int mt = 0; mt < 4; mt++)
        aptr[mt] = smem_u32(&As[(wm * 64 + mt * 16 + ar) * 64]);
    const int nr = (lane & 7) + ((lane >> 4) & 1) * 8;
    const int bmask = lane & 7;
    bptr[0] = smem_u32(&Bs[(wn * 32 + nr) * 64]);
    bptr[1] = smem_u32(&Bs[(wn * 32 + 16 + nr) * 64]);
    const int agq = lane >> 4;
    const int bgq = (lane >> 3) & 1;

    asm volatile("cp.async.wait_group 0;");
    __syncthreads();

    #pragma unroll
    for (int kk = 0; kk < 8; kk++) {
        uint32_t gA = (uint32_t)(((kk * 2 + agq) ^ amask) * 16);
        uint32_t gB = (uint32_t)(((kk * 2 + bgq) ^ bmask) * 16);
        uint32_t af[4][4], b0[4], b1[4];
        #pragma unroll
        for (int mt = 0; mt < 4; mt++)
            LDSM_X4(af[mt][0], af[mt][1], af[mt][2], af[mt][3], aptr[mt] + gA);
        LDSM_X4(b0[0], b0[1], b0[2], b0[3], bptr[0] + gB);
        LDSM_X4(b1[0], b1[1], b1[2], b1[3], bptr[1] + gB);
        #pragma unroll
        for (int mt = 0; mt < 4; mt++) {
            MMA16816(c[mt][0], af[mt][0], af[mt][1], af[mt][2], af[mt][3], b0[0], b0[1]);
            MMA16816(c[mt][1], af[mt][0], af[mt][1], af[mt][2], af[mt][3], b0[2], b0[3]);
            MMA16816(c[mt][2], af[mt][0], af[mt][1], af[mt][2], af[mt][3], b1[0], b1[1]);
            MMA16816(c[mt][3], af[mt][0], af[mt][1], af[mt][2], af[mt][3], b1[2], b1[3]);
        }
    }

    const int l2 = t4 * 2;
    if (y == 1) {
        #pragma unroll
        for (int mt = 0; mt < 4; mt++) {
            #pragma unroll
            for (int nt = 0; nt < 4; nt++) {
                int r = row0 + wm * 64 + mt * 16 + g;
                int cc = wn * 32 + nt * 8 + l2;
                float2 b2 = *(const float2*)(biasv + cc);
                if (r < M)
                    *(float2*)(acc + (size_t)r * 128 + cc) =
                        make_float2(c[mt][nt][0] + b2.x, c[mt][nt][1] + b2.y);
                if (r + 8 < M)
                    *(float2*)(acc + (size_t)(r + 8) * 128 + cc) =
                        make_float2(c[mt][nt][2] + b2.x, c[mt][nt][3] + b2.y);
            }
        }
    } else {
        const float* att = (y == 0) ? att_s : att_d;
        float* adst = (y == 0) ? g_as : g_ad;
        float2 attv[4];
        #pragma unroll
        for (int nt = 0; nt < 4; nt++)
            attv[nt] = *(const float2*)(att + wn * 32 + nt * 8 + l2);

        #pragma unroll
        for (int mt = 0; mt < 4; mt++) {
            int r = row0 + wm * 64 + mt * 16 + g;
            float p0 = 0.f, p1 = 0.f;
            #pragma unroll
            for (int nt = 0; nt < 4; nt++) {
                p0 = fmaf(c[mt][nt][0], attv[nt].x, fmaf(c[mt][nt][1], attv[nt].y, p0));
                p1 = fmaf(c[mt][nt][2], attv[nt].x, fmaf(c[mt][nt][3], attv[nt].y, p1));
                if (y == 0) {
                    int cc = wn * 32 + nt * 8 + l2;
                    if (r < M)
                        *(half2*)(g_xs_h + (size_t)r * 128 + cc) =
                            __floats2half2_rn(c[mt][nt][0], c[mt][nt][1]);
                    if (r + 8 < M)
                        *(half2*)(g_xs_h + (size_t)(r + 8) * 128 + cc) =
                            __floats2half2_rn(c[mt][nt][2], c[mt][nt][3]);
                }
            }
            p0 += __shfl_xor_sync(0xFFFFFFFFu, p0, 1);
            p0 += __shfl_xor_sync(0xFFFFFFFFu, p0, 2);
            p1 += __shfl_xor_sync(0xFFFFFFFFu, p1, 1);
            p1 += __shfl_xor_sync(0xFFFFFFFFu, p1, 2);
            if ((lane & 3) == 0) {
                if (r < M)     adst[r * 4 + wn] = p0;
                if (r + 8 < M) adst[(r + 8) * 4 + wn] = p1;
            }
        }
    }
}

// ------------------------- fused edge softmax-SpMM (+LN) -----------------
// 128-thread blocks, 12 CTA/SM (<=42 regs) for latency hiding.
template <bool DO_LN>
__global__ __launch_bounds__(128, 12) void edge_fused(float* __restrict__ io,
                                                      const float* __restrict__ gamma,
                                                      const float* __restrict__ beta,
                                                      int n)
{
    __shared__ float4 s_w4[4][32];
    __shared__ int    s_src[4][32];
    const int wid = threadIdx.x >> 5;
    const int lane = threadIdx.x & 31;
    if (DO_LN && blockIdx.x == 0 && threadIdx.x < 4)
        g_barf[threadIdx.x] = 0;                       // reset csr grid-barrier flags
    int node = (blockIdx.x * blockDim.x + threadIdx.x) >> 5;
    if (node >= n) return;

    const int rs = g_rowptr[node], re = g_rowptr[node + 1];
    const float4 ad4 = *(const float4*)(g_ad + (size_t)node * 4);
    const int hh = (lane & 15) >> 2;
    const int feat = (lane & 15) * 8;

    float acc[8] = {0.f, 0.f, 0.f, 0.f, 0.f, 0.f, 0.f, 0.f};
    float4 wsum = make_float4(0.f, 0.f, 0.f, 0.f);

    for (int base = rs; base < re; base += 32) {
        int e = base + lane;
        int sreg = 0;
        float4 w4 = make_float4(0.f, 0.f, 0.f, 0.f);
        if (e < re) {
            sreg = g_csrc[e];
            float4 a = *(const float4*)(g_as + (size_t)sreg * 4);
            float vx = a.x + ad4.x, vy = a.y + ad4.y;
            float vz = a.z + ad4.z, vw = a.w + ad4.w;
            vx = vx > 0.f ? vx : LRELU * vx;
            vy = vy > 0.f ? vy : LRELU * vy;
            vz = vz > 0.f ? vz : LRELU * vz;
            vw = vw > 0.f ? vw : LRELU * vw;
            w4.x = __expf(vx); w4.y = __expf(vy);
            w4.z = __expf(vz); w4.w = __expf(vw);
        }
        wsum.x += w4.x; wsum.y += w4.y; wsum.z += w4.z; wsum.w += w4.w;
        s_w4[wid][lane] = w4;
        s_src[wid][lane] = sreg;
        __syncwarp();

        int cnt = min(32, re - base);
        int iters = (cnt + 1) >> 1;
        #pragma unroll 4
        for (int it = 0; it < iters; it++) {
            int jsel = 2 * it + (lane >> 4);
            int sj = s_src[wid][jsel];
            float wv = ((const float*)&s_w4[wid][jsel])[hh];
            uint4 raw = *(const uint4*)(g_xs_h + (size_t)sj * 128 + feat);
            float2 f0 = __half22float2(*(half2*)&raw.x);
            float2 f1 = __half22float2(*(half2*)&raw.y);
            float2 f2 = __half22float2(*(half2*)&raw.z);
            float2 f3 = __half22float2(*(half2*)&raw.w);
            acc[0] = fmaf(wv, f0.x, acc[0]); acc[1] = fmaf(wv, f0.y, acc[1]);
            acc[2] = fmaf(wv, f1.x, acc[2]); acc[3] = fmaf(wv, f1.y, acc[3]);
            acc[4] = fmaf(wv, f2.x, acc[4]); acc[5] = fmaf(wv, f2.y, acc[5]);
            acc[6] = fmaf(wv, f3.x, acc[6]); acc[7] = fmaf(wv, f3.y, acc[7]);
        }
        __syncwarp();
    }

    #pragma unroll
    for (int k = 0; k < 8; k++)
        acc[k] += __shfl_xor_sync(0xFFFFFFFFu, acc[k], 16);

    #pragma unroll
    for (int m = 16; m >= 1; m >>= 1) {
        wsum.x += __shfl_xor_sync(0xFFFFFFFFu, wsum.x, m);
        wsum.y += __shfl_xor_sync(0xFFFFFFFFu, wsum.y, m);
        wsum.z += __shfl_xor_sync(0xFFFFFFFFu, wsum.z, m);
        wsum.w += __shfl_xor_sync(0xFFFFFFFFu, wsum.w, m);
    }
    float dh = (hh < 2) ? (hh == 0 ? wsum.x : wsum.y) : (hh == 2 ? wsum.z : wsum.w);
    float inv = __fdividef(1.f, dh + 1e-16f);

    float4 i0 = *(const float4*)(io + (size_t)node * 128 + feat);
    float4 i1 = *(const float4*)(io + (size_t)node * 128 + feat + 4);
    float o[8];
    o[0] = fmaf(acc[0], inv, i0.x); o[1] = fmaf(acc[1], inv, i0.y);
    o[2] = fmaf(acc[2], inv, i0.z); o[3] = fmaf(acc[3], inv, i0.w);
    o[4] = fmaf(acc[4], inv, i1.x); o[5] = fmaf(acc[5], inv, i1.y);
    o[6] = fmaf(acc[6], inv, i1.z); o[7] = fmaf(acc[7], inv, i1.w);

    if (DO_LN) {
        float sum = 0.f, sq = 0.f;
        #pragma unroll
        for (int k = 0; k < 8; k++) { sum += o[k]; sq = fmaf(o[k], o[k], sq); }
        #pragma unroll
        for (int m = 1; m <= 16; m <<= 1) {
            sum += __shfl_xor_sync(0xFFFFFFFFu, sum, m);
            sq  += __shfl_xor_sync(0xFFFFFFFFu, sq, m);
        }
        float mean = sum * (1.f / 256.f);        // lanes duplicated x2
        float var  = sq * (1.f / 256.f) - mean * mean;
        float rstd = rsqrtf(var + LN_EPS);
        float4 ga = *(const float4*)(gamma + feat);
        float4 gb = *(const float4*)(gamma + feat + 4);
        float4 ba = *(const float4*)(beta + feat);
        float4 bb = *(const float4*)(beta + feat + 4);
        float r[8];
        r[0] = fmaxf(0.f, (o[0] - mean) * rstd * ga.x + ba.x);
        r[1] = fmaxf(0.f, (o[1] - mean) * rstd * ga.y + ba.y);
        r[2] = fmaxf(0.f, (o[2] - mean) * rstd * ga.z + ba.z);
        r[3] = fmaxf(0.f, (o[3] - mean) * rstd * ga.w + ba.w);
        r[4] = fmaxf(0.f, (o[4] - mean) * rstd * gb.x + bb.x);
        r[5] = fmaxf(0.f, (o[5] - mean) * rstd * gb.y + bb.y);
        r[6] = fmaxf(0.f, (o[6] - mean) * rstd * gb.z + bb.z);
        r[7] = fmaxf(0.f, (o[7] - mean) * rstd * gb.w + bb.w);
        if (lane < 16) {
            __half2 hh2[4];
            hh2[0] = __floats2half2_rn(r[0], r[1]);
            hh2[1] = __floats2half2_rn(r[2], r[3]);
            hh2[2] = __floats2half2_rn(r[4], r[5]);
            hh2[3] = __floats2half2_rn(r[6], r[7]);
            *(uint4*)(g_h_h + (size_t)node * 128 + feat) = *(uint4*)hh2;
        }
    } else {
        if (lane < 16) {
            *(float4*)(io + (size_t)node * 128 + feat)     = make_float4(o[0], o[1], o[2], o[3]);
            *(float4*)(io + (size_t)node * 128 + feat + 4) = make_float4(o[4], o[5], o[6], o[7]);
        }
    }
}

// ------------------------- driver ----------------------------------------
extern "C" void kernel_launch(void* const* d_in, const int* in_sizes, int n_in,
                              void* d_out, int out_size)
{
    const float* x        = (const float*)d_in[0];
    const int*   ei       = (const int*)  d_in[1];
    const float* W1_src   = (const float*)d_in[2];
    const float* W1_dst   = (const float*)d_in[3];
    const float* att1_src = (const float*)d_in[4];
    const float* att1_dst = (const float*)d_in[5];
    const float* b1       = (const float*)d_in[6];
    const float* Wl1      = (const float*)d_in[7];
    const float* bl1      = (const float*)d_in[8];
    const float* gamma    = (const float*)d_in[9];
    const float* beta     = (const float*)d_in[10];
    const float* W2_src   = (const float*)d_in[11];
    const float* W2_dst   = (const float*)d_in[12];
    const float* att2_src = (const float*)d_in[13];
    const float* att2_dst = (const float*)d_in[14];
    const float* b2       = (const float*)d_in[15];
    const float* Wl2      = (const float*)d_in[16];
    const float* bl2      = (const float*)d_in[17];
    float* out = (float*)d_out;

    const int n = NN;
    const int E = EE;
    const int* src = ei;
    const int* dst = ei + E;

    void* p;
    cudaGetSymbolAddress(&p, g_acc1);  float* acc1 = (float*)p;
    cudaGetSymbolAddress(&p, g_Wp);    __half2* wp = (__half2*)p;
    cudaGetSymbolAddress(&p, g_biasA); float* bias = (float*)p;
    cudaGetSymbolAddress(&p, g_x_h);   __half* xh = (__half*)p;
    cudaGetSymbolAddress(&p, g_h_h);   __half* hh = (__half*)p;

    const int SMEM = 2 * 128 * 64 * 4;   // 65536 B exact -> 2 CTAs/SM
    cudaFuncSetAttribute(gemm_h, cudaFuncAttributeMaxDynamicSharedMemorySize, SMEM);

    static cudaStream_t s2 = nullptr;
    static cudaEvent_t ev_fork = nullptr, ev_join = nullptr;
    if (!s2) {
        cudaStreamCreateWithFlags(&s2, cudaStreamNonBlocking);
        cudaEventCreateWithFlags(&ev_fork, cudaEventDisableTiming);
        cudaEventCreateWithFlags(&ev_join, cudaEventDisableTiming);
    }

    dim3 gemm_grid((n + 127) / 128, 3);
    int node_blocks = (n + 3) / 4;           // 128-thread blocks, 4 warps = 4 nodes each

    // fork: csr_all runs concurrently with prep_all + gemm1
    cudaEventRecord(ev_fork, 0);
    cudaStreamWaitEvent(s2, ev_fork, 0);
    csr_all<<<NBLK, 1024, 0, s2>>>(src, dst, E, n);
    cudaEventRecord(ev_join, s2);

    prep_all<<<3317, 256>>>(x, W1_src, W1_dst, Wl1, bl1, b1,
                            W2_src, W2_dst, Wl2, bl2, b2);
    gemm_h<<<gemm_grid, 256, SMEM>>>(xh, acc1, wp, bias,
                                     att1_src, att1_dst, n);

    cudaStreamWaitEvent(0, ev_join, 0);
    edge_fused<true><<<node_blocks, 128>>>(acc1, gamma, beta, n);
    gemm_h<<<gemm_grid, 256, SMEM>>>(hh, out, wp + 384 * 64, bias + 128,
                                     att2_src, att2_dst, n);
    edge_fused<false><<<node_blocks, 128>>>(out, nullptr, nullptr, n);
}

// round 16
// speedup vs baseline: 1.2841x; 1.0795x over previous
#include <cuda_runtime.h>
#include <cuda_bf16.h>
#include <cuda_fp16.h>
#include <cstdint>

#define NN 50000
#define EE 800000
#define LRELU 0.2f
#define LN_EPS 1e-5f
#define NBLK 148

// ------------------------- scratch (device globals) ----------------------
__device__ __align__(16) __half g_x_h[(size_t)NN * 128];    // fp16 input x
__device__ __align__(16) __half g_h_h[(size_t)NN * 128];    // fp16 layer1 out
__device__ __align__(16) __half g_xs_h[(size_t)NN * 128];   // fp16 xs
__device__ float g_acc1[(size_t)NN * 128];
__device__ float g_as[NN * 4];
__device__ float g_ad[NN * 4];
__device__ __align__(16) __half2 g_Wp[2 * 384 * 64];   // [layer][col 384][k2 64] n-major
__device__ float g_biasA[2 * 128];
// CSR
__device__ int g_cnt[NN];
__device__ int g_rowptr[NN + 1];
__device__ int g_woff[NN];
__device__ int g_csrc[EE];
__device__ int g_bsum[NBLK];
// software grid barrier state
__device__ int g_barc[4];
__device__ int g_barf[4];

// ------------------------- helpers ---------------------------------------
__device__ __forceinline__ uint32_t smem_u32(const void* p)
{
    return (uint32_t)__cvta_generic_to_shared(p);
}

#define LDSM_X4(d0, d1, d2, d3, addr)                                            \
    asm volatile("ldmatrix.sync.aligned.m8n8.x4.shared.b16 {%0,%1,%2,%3}, [%4];" \
                 : "=r"(d0), "=r"(d1), "=r"(d2), "=r"(d3) : "r"(addr))

#define MMA16816(C, A0, A1, A2, A3, B0, B1)                                  \
    asm volatile("mma.sync.aligned.m16n8k16.row.col.f32.f16.f16.f32 "        \
                 "{%0,%1,%2,%3}, {%4,%5,%6,%7}, {%8,%9}, {%0,%1,%2,%3};"     \
                 : "+f"((C)[0]), "+f"((C)[1]), "+f"((C)[2]), "+f"((C)[3])    \
                 : "r"(A0), "r"(A1), "r"(A2), "r"(A3), "r"(B0), "r"(B1))

#define CP_ASYNC16(dst, src, sz)                                             \
    asm volatile("cp.async.cg.shared.global [%0], [%1], 16, %2;"             \
                 :: "r"(dst), "l"(src), "r"(sz))

// ------------------------- merged prep: x->fp16 + weight pack ------------
__global__ void prep_all(const float* __restrict__ X,
                         const float* __restrict__ W1s, const float* __restrict__ W1d,
                         const float* __restrict__ Wl1, const float* __restrict__ bl1,
                         const float* __restrict__ b1,
                         const float* __restrict__ W2s, const float* __restrict__ W2d,
                         const float* __restrict__ Wl2, const float* __restrict__ bl2,
                         const float* __restrict__ b2)
{
    if (blockIdx.x < 3125) {
        int i = blockIdx.x * 256 + threadIdx.x;           // < 800000 = NN*16
        const float4* p = (const float4*)X + (size_t)i * 2;
        float4 a = p[0], b = p[1];
        __half2 h[4];
        h[0] = __floats2half2_rn(a.x, a.y); h[1] = __floats2half2_rn(a.z, a.w);
        h[2] = __floats2half2_rn(b.x, b.y); h[3] = __floats2half2_rn(b.z, b.w);
        *(uint4*)(g_x_h + (size_t)i * 8) = *(uint4*)h;
    } else {
        int i = (blockIdx.x - 3125) * 256 + threadIdx.x;  // < 49152
        int layer = i >= 24576;
        int j = i - layer * 24576;
        int col = j >> 6, k2 = j & 63;
        int cc = col & 127;
        const float* W;
        if (col < 128)      W = layer ? W2s : W1s;
        else if (col < 256) W = layer ? Wl2 : Wl1;
        else                W = layer ? W2d : W1d;
        g_Wp[i] = __floats2half2_rn(W[(2 * k2) * 128 + cc], W[(2 * k2 + 1) * 128 + cc]);
        if (i < 128) {
            g_biasA[i]       = bl1[i] + b1[i];
            g_biasA[128 + i] = bl2[i] + b2[i];
        }
    }
}

// ------------------------- software grid barrier -------------------------
__device__ __forceinline__ void gbar(int k)
{
    __syncthreads();
    if (threadIdx.x == 0) {
        __threadfence();
        int t = atomicAdd(&g_barc[k], 1);
        if (t == NBLK - 1) {
            g_barc[k] = 0;
            __threadfence();
            atomicExch(&g_barf[k], 1);
        } else {
            while (atomicAdd(&g_barf[k], 0) == 0) __nanosleep(64);
        }
        __threadfence();
    }
    __syncthreads();
}

// ------------------------- single-kernel CSR build -----------------------
__global__ __launch_bounds__(1024) void csr_all(const int* __restrict__ src,
                                                const int* __restrict__ dst,
                                                int E, int n)
{
    __shared__ int s[1024];
    __shared__ int sb[256];
    const int tid = threadIdx.x;
    const int gid = blockIdx.x * 1024 + tid;
    const int GT = NBLK * 1024;

    for (int i = gid; i < n; i += GT) g_cnt[i] = 0;
    gbar(0);
    for (int e = gid; e < E; e += GT) atomicAdd(&g_cnt[dst[e]], 1);
    gbar(1);
    const int CH = (n + NBLK - 1) / NBLK;
    const int base = blockIdx.x * CH;
    int myc = 0;
    if (tid < CH && base + tid < n) myc = g_cnt[base + tid];
    s[tid] = myc;
    __syncthreads();
    for (int off = 1; off < 1024; off <<= 1) {
        int v = (tid >= off) ? s[tid - off] : 0;
        __syncthreads();
        s[tid] += v;
        __syncthreads();
    }
    int myincl = s[tid];
    if (tid == 1023) g_bsum[blockIdx.x] = s[1023];
    gbar(2);
    if (tid < 256) sb[tid] = (tid < NBLK) ? g_bsum[tid] : 0;
    __syncthreads();
    for (int off = 1; off < 256; off <<= 1) {
        int v = 0;
        if (tid < 256 && tid >= off) v = sb[tid - off];
        __syncthreads();
        if (tid < 256) sb[tid] += v;
        __syncthreads();
    }
    int off0 = (blockIdx.x == 0) ? 0 : sb[blockIdx.x - 1];
    if (tid < CH && base + tid < n) {
        int v = off0 + myincl - myc;
        g_rowptr[base + tid] = v;
        g_woff[base + tid] = v;
    }
    if (blockIdx.x == 0 && tid == 0) g_rowptr[n] = E;
    gbar(3);
    for (int e = gid; e < E; e += GT) {
        int d = dst[e];
        int pz = atomicAdd(&g_woff[d], 1);
        g_csrc[pz] = src[e];
    }
}

// ------------------------- fp16 GEMM: K-resident, swizzled (2 CTA/SM) ----
__global__ __launch_bounds__(256, 2) void gemm_h(const __half* __restrict__ Ah,
                                                 float* __restrict__ acc,
                                                 const __half2* __restrict__ Wp,
                                                 const float* __restrict__ biasv,
                                                 const float* __restrict__ att_s,
                                                 const float* __restrict__ att_d,
                                                 int M)
{
    extern __shared__ __half2 smp[];
    __half2* As = smp;                 // [128][64] half2, swizzled granules
    __half2* Bs = smp + 128 * 64;

    const int tid = threadIdx.x;
    const int lane = tid & 31;
    const int warp = tid >> 5;
    const int wm = warp >> 2;
    const int wn = warp & 3;
    const int row0 = blockIdx.x * 128;
    const int y = blockIdx.y;
    const int col0 = y * 128;
    const int g = lane >> 2;
    const int t4 = lane & 3;

    #pragma unroll
    for (int j = 0; j < 8; j++) {
        int idx = tid + j * 256;
        int row = idx >> 4, part = idx & 15;
        int grow = row0 + row;
        const __half* srcp = Ah + (size_t)(grow < M ? grow : 0) * 128 + part * 8;
        uint32_t dstu = smem_u32(&As[row * 64 + (part ^ (row & 7)) * 4]);
        CP_ASYNC16(dstu, srcp, (grow < M) ? 16 : 0);
    }
    #pragma unroll
    for (int j = 0; j < 8; j++) {
        int idx = tid + j * 256;
        int col = idx >> 4, part = idx & 15;
        const __half2* srcp = Wp + (size_t)(col0 + col) * 64 + part * 4;
        uint32_t dstu = smem_u32(&Bs[col * 64 + (part ^ (col & 7)) * 4]);
        CP_ASYNC16(dstu, srcp, 16);
    }
    asm volatile("cp.async.commit_group;");

    float c[4][4][4];
    #pragma unroll
    for (int i = 0; i < 4; i++)
        #pragma unroll
        for (int j = 0; j < 4; j++)
            #pragma unroll
            for (int q = 0; q < 4; q++) c[i][j][q] = 0.f;

    uint32_t aptr[4], bptr[2];
    const int ar = lane & 15;
    const int amask = ar & 7;
    #pragma unroll
    for (int mt = 0; mt < 4; mt++)
        aptr[mt] = smem_u32(&As[(wm * 64 + mt * 16 + ar) * 64]);
    const int nr = (lane & 7) + ((lane >> 4) & 1) * 8;
    const int bmask = lane & 7;
    bptr[0] = smem_u32(&Bs[(wn * 32 + nr) * 64]);
    bptr[1] = smem_u32(&Bs[(wn * 32 + 16 + nr) * 64]);
    const int agq = lane >> 4;
    const int bgq = (lane >> 3) & 1;

    asm volatile("cp.async.wait_group 0;");
    __syncthreads();

    #pragma unroll
    for (int kk = 0; kk < 8; kk++) {
        uint32_t gA = (uint32_t)(((kk * 2 + agq) ^ amask) * 16);
        uint32_t gB = (uint32_t)(((kk * 2 + bgq) ^ bmask) * 16);
        uint32_t af[4][4], b0[4], b1[4];
        #pragma unroll
        for (int mt = 0; mt < 4; mt++)
            LDSM_X4(af[mt][0], af[mt][1], af[mt][2], af[mt][3], aptr[mt] + gA);
        LDSM_X4(b0[0], b0[1], b0[2], b0[3], bptr[0] + gB);
        LDSM_X4(b1[0], b1[1], b1[2], b1[3], bptr[1] + gB);
        #pragma unroll
        for (int mt = 0; mt < 4; mt++) {
            MMA16816(c[mt][0], af[mt][0], af[mt][1], af[mt][2], af[mt][3], b0[0], b0[1]);
            MMA16816(c[mt][1], af[mt][0], af[mt][1], af[mt][2], af[mt][3], b0[2], b0[3]);
            MMA16816(c[mt][2], af[mt][0], af[mt][1], af[mt][2], af[mt][3], b1[0], b1[1]);
            MMA16816(c[mt][3], af[mt][0], af[mt][1], af[mt][2], af[mt][3], b1[2], b1[3]);
        }
    }

    const int l2 = t4 * 2;
    if (y == 1) {
        #pragma unroll
        for (int mt = 0; mt < 4; mt++) {
            #pragma unroll
            for (int nt = 0; nt < 4; nt++) {
                int r = row0 + wm * 64 + mt * 16 + g;
                int cc = wn * 32 + nt * 8 + l2;
                float2 b2 = *(const float2*)(biasv + cc);
                if (r < M)
                    *(float2*)(acc + (size_t)r * 128 + cc) =
                        make_float2(c[mt][nt][0] + b2.x, c[mt][nt][1] + b2.y);
                if (r + 8 < M)
                    *(float2*)(acc + (size_t)(r + 8) * 128 + cc) =
                        make_float2(c[mt][nt][2] + b2.x, c[mt][nt][3] + b2.y);
            }
        }
    } else {
        const float* att = (y == 0) ? att_s : att_d;
        float* adst = (y == 0) ? g_as : g_ad;
        float2 attv[4];
        #pragma unroll
        for (int nt = 0; nt < 4; nt++)
            attv[nt] = *(const float2*)(att + wn * 32 + nt * 8 + l2);

        #pragma unroll
        for (int mt = 0; mt < 4; mt++) {
            int r = row0 + wm * 64 + mt * 16 + g;
            float p0 = 0.f, p1 = 0.f;
            #pragma unroll
            for (int nt = 0; nt < 4; nt++) {
                p0 = fmaf(c[mt][nt][0], attv[nt].x, fmaf(c[mt][nt][1], attv[nt].y, p0));
                p1 = fmaf(c[mt][nt][2], attv[nt].x, fmaf(c[mt][nt][3], attv[nt].y, p1));
                if (y == 0) {
                    int cc = wn * 32 + nt * 8 + l2;
                    if (r < M)
                        *(half2*)(g_xs_h + (size_t)r * 128 + cc) =
                            __floats2half2_rn(c[mt][nt][0], c[mt][nt][1]);
                    if (r + 8 < M)
                        *(half2*)(g_xs_h + (size_t)(r + 8) * 128 + cc) =
                            __floats2half2_rn(c[mt][nt][2], c[mt][nt][3]);
                }
            }
            p0 += __shfl_xor_sync(0xFFFFFFFFu, p0, 1);
            p0 += __shfl_xor_sync(0xFFFFFFFFu, p0, 2);
            p1 += __shfl_xor_sync(0xFFFFFFFFu, p1, 1);
            p1 += __shfl_xor_sync(0xFFFFFFFFu, p1, 2);
            if ((lane & 3) == 0) {
                if (r < M)     adst[r * 4 + wn] = p0;
                if (r + 8 < M) adst[(r + 8) * 4 + wn] = p1;
            }
        }
    }
}

// ------------------------- fused edge softmax-SpMM (+LN) -----------------
// Half-warp per node (mean degree 16): 16-lane chunks, lane owns 8 features
// (full 256B fp16 row per half-warp), no cross-half combine needed.
template <bool DO_LN>
__global__ __launch_bounds__(128, 12) void edge_fused(float* __restrict__ io,
                                                      const float* __restrict__ gamma,
                                                      const float* __restrict__ beta,
                                                      int n)
{
    __shared__ float4 s_w4[4][32];
    __shared__ int    s_src[4][32];
    const int wid = threadIdx.x >> 5;
    const int lane = threadIdx.x & 31;
    if (DO_LN && blockIdx.x == 0 && threadIdx.x < 4)
        g_barf[threadIdx.x] = 0;                       // reset csr grid-barrier flags

    const int sl = lane & 15;                          // sub-lane within half
    const int half16 = lane & 16;                      // 0 or 16
    const int node = blockIdx.x * 8 + wid * 2 + (lane >> 4);
    const bool valid = node < n;

    int rs = 0, re = 0;
    float4 ad4 = make_float4(0.f, 0.f, 0.f, 0.f);
    if (valid) {
        rs = g_rowptr[node];
        re = g_rowptr[node + 1];
        ad4 = *(const float4*)(g_ad + (size_t)node * 4);
    }
    int nch = (re - rs + 15) >> 4;
    int nmax = max(nch, __shfl_xor_sync(0xFFFFFFFFu, nch, 16));

    const int hh = sl >> 2;                            // head of my 8 features
    const int feat = sl * 8;

    float acc[8] = {0.f, 0.f, 0.f, 0.f, 0.f, 0.f, 0.f, 0.f};
    float4 wsum = make_float4(0.f, 0.f, 0.f, 0.f);

    for (int t = 0; t < nmax; t++) {
        int base = rs + t * 16;
        int e = base + sl;
        int sreg = 0;
        float4 w4 = make_float4(0.f, 0.f, 0.f, 0.f);
        if (e < re) {
            sreg = g_csrc[e];
            float4 a = *(const float4*)(g_as + (size_t)sreg * 4);
            float vx = a.x + ad4.x, vy = a.y + ad4.y;
            float vz = a.z + ad4.z, vw = a.w + ad4.w;
            vx = vx > 0.f ? vx : LRELU * vx;
            vy = vy > 0.f ? vy : LRELU * vy;
            vz = vz > 0.f ? vz : LRELU * vz;
            vw = vw > 0.f ? vw : LRELU * vw;
            w4.x = __expf(vx); w4.y = __expf(vy);
            w4.z = __expf(vz); w4.w = __expf(vw);
        }
        wsum.x += w4.x; wsum.y += w4.y; wsum.z += w4.z; wsum.w += w4.w;
        s_w4[wid][lane] = w4;
        s_src[wid][lane] = sreg;
        __syncwarp();

        int cnt = re - base;
        cnt = cnt < 0 ? 0 : (cnt > 16 ? 16 : cnt);
        #pragma unroll 4
        for (int it = 0; it < cnt; it++) {
            int slot = half16 + it;
            int sj = s_src[wid][slot];
            float wv = ((const float*)&s_w4[wid][slot])[hh];
            uint4 raw = *(const uint4*)(g_xs_h + (size_t)sj * 128 + feat);
            float2 f0 = __half22float2(*(half2*)&raw.x);
            float2 f1 = __half22float2(*(half2*)&raw.y);
            float2 f2 = __half22float2(*(half2*)&raw.z);
            float2 f3 = __half22float2(*(half2*)&raw.w);
            acc[0] = fmaf(wv, f0.x, acc[0]); acc[1] = fmaf(wv, f0.y, acc[1]);
            acc[2] = fmaf(wv, f1.x, acc[2]); acc[3] = fmaf(wv, f1.y, acc[3]);
            acc[4] = fmaf(wv, f2.x, acc[4]); acc[5] = fmaf(wv, f2.y, acc[5]);
            acc[6] = fmaf(wv, f3.x, acc[6]); acc[7] = fmaf(wv, f3.y, acc[7]);
        }
        __syncwarp();
    }

    // denominator reduce within half-warp (16 lanes)
    #pragma unroll
    for (int m = 8; m >= 1; m >>= 1) {
        wsum.x += __shfl_xor_sync(0xFFFFFFFFu, wsum.x, m);
        wsum.y += __shfl_xor_sync(0xFFFFFFFFu, wsum.y, m);
        wsum.z += __shfl_xor_sync(0xFFFFFFFFu, wsum.z, m);
        wsum.w += __shfl_xor_sync(0xFFFFFFFFu, wsum.w, m);
    }
    float dh = (hh < 2) ? (hh == 0 ? wsum.x : wsum.y) : (hh == 2 ? wsum.z : wsum.w);
    float inv = __fdividef(1.f, dh + 1e-16f);

    if (!valid) return;

    float4 i0 = *(const float4*)(io + (size_t)node * 128 + feat);
    float4 i1 = *(const float4*)(io + (size_t)node * 128 + feat + 4);
    float o[8];
    o[0] = fmaf(acc[0], inv, i0.x); o[1] = fmaf(acc[1], inv, i0.y);
    o[2] = fmaf(acc[2], inv, i0.z); o[3] = fmaf(acc[3], inv, i0.w);
    o[4] = fmaf(acc[4], inv, i1.x); o[5] = fmaf(acc[5], inv, i1.y);
    o[6] = fmaf(acc[6], inv, i1.z); o[7] = fmaf(acc[7], inv, i1.w);

    if (DO_LN) {
        float sum = 0.f, sq = 0.f;
        #pragma unroll
        for (int k = 0; k < 8; k++) { sum += o[k]; sq = fmaf(o[k], o[k], sq); }
        #pragma unroll
        for (int m = 1; m <= 8; m <<= 1) {
            sum += __shfl_xor_sync(0xFFFFFFFFu, sum, m);
            sq  += __shfl_xor_sync(0xFFFFFFFFu, sq, m);
        }
        float mean = sum * (1.f / 128.f);
        float var  = sq * (1.f / 128.f) - mean * mean;
        float rstd = rsqrtf(var + LN_EPS);
        float4 ga = *(const float4*)(gamma + feat);
        float4 gb = *(const float4*)(gamma + feat + 4);
        float4 ba = *(const float4*)(beta + feat);
        float4 bb = *(const float4*)(beta + feat + 4);
        float r[8];
        r[0] = fmaxf(0.f, (o[0] - mean) * rstd * ga.x + ba.x);
        r[1] = fmaxf(0.f, (o[1] - mean) * rstd * ga.y + ba.y);
        r[2] = fmaxf(0.f, (o[2] - mean) * rstd * ga.z + ba.z);
        r[3] = fmaxf(0.f, (o[3] - mean) * rstd * ga.w + ba.w);
        r[4] = fmaxf(0.f, (o[4] - mean) * rstd * gb.x + bb.x);
        r[5] = fmaxf(0.f, (o[5] - mean) * rstd * gb.y + bb.y);
        r[6] = fmaxf(0.f, (o[6] - mean) * rstd * gb.z + bb.z);
        r[7] = fmaxf(0.f, (o[7] - mean) * rstd * gb.w + bb.w);
        __half2 hh2[4];
        hh2[0] = __floats2half2_rn(r[0], r[1]);
        hh2[1] = __floats2half2_rn(r[2], r[3]);
        hh2[2] = __floats2half2_rn(r[4], r[5]);
        hh2[3] = __floats2half2_rn(r[6], r[7]);
        *(uint4*)(g_h_h + (size_t)node * 128 + feat) = *(uint4*)hh2;
    } else {
        *(float4*)(io + (size_t)node * 128 + feat)     = make_float4(o[0], o[1], o[2], o[3]);
        *(float4*)(io + (size_t)node * 128 + feat + 4) = make_float4(o[4], o[5], o[6], o[7]);
    }
}

// ------------------------- driver ----------------------------------------
extern "C" void kernel_launch(void* const* d_in, const int* in_sizes, int n_in,
                              void* d_out, int out_size)
{
    const float* x        = (const float*)d_in[0];
    const int*   ei       = (const int*)  d_in[1];
    const float* W1_src   = (const float*)d_in[2];
    const float* W1_dst   = (const float*)d_in[3];
    const float* att1_src = (const float*)d_in[4];
    const float* att1_dst = (const float*)d_in[5];
    const float* b1       = (const float*)d_in[6];
    const float* Wl1      = (const float*)d_in[7];
    const float* bl1      = (const float*)d_in[8];
    const float* gamma    = (const float*)d_in[9];
    const float* beta     = (const float*)d_in[10];
    const float* W2_src   = (const float*)d_in[11];
    const float* W2_dst   = (const float*)d_in[12];
    const float* att2_src = (const float*)d_in[13];
    const float* att2_dst = (const float*)d_in[14];
    const float* b2       = (const float*)d_in[15];
    const float* Wl2      = (const float*)d_in[16];
    const float* bl2      = (const float*)d_in[17];
    float* out = (float*)d_out;

    const int n = NN;
    const int E = EE;
    const int* src = ei;
    const int* dst = ei + E;

    void* p;
    cudaGetSymbolAddress(&p, g_acc1);  float* acc1 = (float*)p;
    cudaGetSymbolAddress(&p, g_Wp);    __half2* wp = (__half2*)p;
    cudaGetSymbolAddress(&p, g_biasA); float* bias = (float*)p;
    cudaGetSymbolAddress(&p, g_x_h);   __half* xh = (__half*)p;
    cudaGetSymbolAddress(&p, g_h_h);   __half* hh = (__half*)p;

    const int SMEM = 2 * 128 * 64 * 4;   // 65536 B exact -> 2 CTAs/SM
    cudaFuncSetAttribute(gemm_h, cudaFuncAttributeMaxDynamicSharedMemorySize, SMEM);

    static cudaStream_t s2 = nullptr;
    static cudaEvent_t ev_fork = nullptr, ev_join = nullptr;
    if (!s2) {
        cudaStreamCreateWithFlags(&s2, cudaStreamNonBlocking);
        cudaEventCreateWithFlags(&ev_fork, cudaEventDisableTiming);
        cudaEventCreateWithFlags(&ev_join, cudaEventDisableTiming);
    }

    dim3 gemm_grid((n + 127) / 128, 3);
    int node_blocks = (n + 7) / 8;           // 128-thread blocks, 2 nodes per warp

    // fork: csr_all runs concurrently with prep_all + gemm1
    cudaEventRecord(ev_fork, 0);
    cudaStreamWaitEvent(s2, ev_fork, 0);
    csr_all<<<NBLK, 1024, 0, s2>>>(src, dst, E, n);
    cudaEventRecord(ev_join, s2);

    prep_all<<<3317, 256>>>(x, W1_src, W1_dst, Wl1, bl1, b1,
                            W2_src, W2_dst, Wl2, bl2, b2);
    gemm_h<<<gemm_grid, 256, SMEM>>>(xh, acc1, wp, bias,
                                     att1_src, att1_dst, n);

    cudaStreamWaitEvent(0, ev_join, 0);
    edge_fused<true><<<node_blocks, 128>>>(acc1, gamma, beta, n);
    gemm_h<<<gemm_grid, 256, SMEM>>>(hh, out, wp + 384 * 64, bias + 128,
                                     att2_src, att2_dst, n);
    edge_fused<false><<<node_blocks, 128>>>(out, nullptr, nullptr, n);
}